// round 6
// baseline (speedup 1.0000x reference)
#include <cuda_runtime.h>
#include <math_constants.h>

#define B_  8
#define LQ_ 2048
#define LK_ 2048
#define D_  128
#define E_  64

// Scratch for projected q, k, v (fp32). 3 x 4 MB, static device arrays (no alloc).
__device__ float g_q[B_ * LQ_ * E_];
__device__ float g_k[B_ * LK_ * E_];
__device__ float g_v[B_ * LK_ * E_];

// Packed f32x2 FMA: d = a * b + d (lanewise lo/hi).
__device__ __forceinline__ void ffma2(unsigned long long& d,
                                      unsigned long long a,
                                      unsigned long long b)
{
    asm("fma.rn.f32x2 %0, %1, %2, %0;" : "+l"(d) : "l"(a), "l"(b));
}

__device__ __forceinline__ float2 upk2(unsigned long long u)
{
    float2 f;
    asm("mov.b64 {%0, %1}, %2;" : "=f"(f.x), "=f"(f.y) : "l"(u));
    return f;
}

// ---------------------------------------------------------------------------
// Projection kernel: out[row, 0:64] = X[row, 0:128] @ W[128, 64]
// grid: (128, 3): x = row tile of 128, y selects (q | k | v). 256 threads.
// ---------------------------------------------------------------------------
#define PROJ_SMEM_BYTES ((128 * 132 + 128 * 68) * 4)

__global__ __launch_bounds__(256, 1) void proj_kernel(
    const float* __restrict__ query,
    const float* __restrict__ key,
    const float* __restrict__ Wq,
    const float* __restrict__ Wk,
    const float* __restrict__ Wv)
{
    extern __shared__ float smem[];
    float* sX = smem;             // [128][132]
    float* sW = smem + 128 * 132; // [128][68]

    const float* X;
    const float* W;
    float* out;
    if (blockIdx.y == 0)      { X = query; W = Wq; out = g_q; }
    else if (blockIdx.y == 1) { X = key;   W = Wk; out = g_k; }
    else                      { X = key;   W = Wv; out = g_v; }

    const int tid = threadIdx.x;
    const int tx = tid & 15;
    const int ty = tid >> 4;
    const int row0 = blockIdx.x * 128;

    for (int i = tid; i < 128 * 16; i += 256) {
        int r = i >> 4, c4 = i & 15;
        float4 w = ((const float4*)(W + r * 64))[c4];
        *(float4*)(sW + r * 68 + c4 * 4) = w;
    }
    for (int i = tid; i < 128 * 32; i += 256) {
        int r = i >> 5, c4 = i & 31;
        float4 x = ((const float4*)(X + (size_t)(row0 + r) * D_))[c4];
        *(float4*)(sX + r * 132 + c4 * 4) = x;
    }
    __syncthreads();

    float acc[8][4];
#pragma unroll
    for (int i = 0; i < 8; i++)
#pragma unroll
        for (int j = 0; j < 4; j++) acc[i][j] = 0.0f;

    for (int k = 0; k < 128; k += 4) {
        float4 xv[8];
#pragma unroll
        for (int i = 0; i < 8; i++)
            xv[i] = *(float4*)(sX + (ty + 16 * i) * 132 + k);
#pragma unroll
        for (int kk = 0; kk < 4; kk++) {
            float4 wv = *(float4*)(sW + (k + kk) * 68 + tx * 4);
#pragma unroll
            for (int i = 0; i < 8; i++) {
                float a = ((const float*)&xv[i])[kk];
                acc[i][0] += a * wv.x;
                acc[i][1] += a * wv.y;
                acc[i][2] += a * wv.z;
                acc[i][3] += a * wv.w;
            }
        }
    }

#pragma unroll
    for (int i = 0; i < 8; i++) {
        float4 r4 = make_float4(acc[i][0], acc[i][1], acc[i][2], acc[i][3]);
        *(float4*)(out + (size_t)(row0 + ty + 16 * i) * E_ + tx * 4) = r4;
    }
}

// ---------------------------------------------------------------------------
// Flash attention kernel, 512 threads.
// grid: (16, 8): x = q tile (128 rows), y = batch.
// Thread (tx = tid&15, ty = tid>>4 in 0..31):
//   S tile: 4 rows (ty + 32*i) x 8 cols ({tx*4..+3, 64+tx*4..+3})
//   O tile: 4 rows x 4 cols (tx*4..+3)
// QK^T uses packed fma.rn.f32x2 with Q duplicated in smem so the packed
// broadcast operand (q,q) is a single conflict-free LDS.64.
// Smem: Qd[128][132] (dup), Kt[64][132] (transposed), V[128][68], P[128][132].
// ---------------------------------------------------------------------------
#define FLASH_SMEM_BYTES ((128 * 132 + 64 * 132 + 128 * 68 + 128 * 132) * 4)

__global__ __launch_bounds__(512, 1) void flash_kernel(float* __restrict__ out)
{
    extern __shared__ float smem[];
    float* sQd = smem;                   // [128][132] duplicated q pairs
    float* sKt = sQd + 128 * 132;        // [64][132]
    float* sV  = sKt + 64 * 132;         // [128][68]
    float* sP  = sV + 128 * 68;          // [128][132]

    const int tid = threadIdx.x;
    const int tx = tid & 15;
    const int ty = tid >> 4;             // 0..31
    const int b = blockIdx.y;
    const int q0 = blockIdx.x * 128;

    const float* qptr = g_q + ((size_t)b * LQ_ + q0) * E_;
    const float* kptr = g_k + (size_t)b * LK_ * E_;
    const float* vptr = g_v + (size_t)b * LK_ * E_;

    // Load Q tile duplicated: sQd[r][2e+0] = sQd[r][2e+1] = q[r][e]
    for (int i = tid; i < 2048; i += 512) {
        int r = i >> 4, c4 = i & 15;
        float4 q = ((const float4*)(qptr + r * E_))[c4];
        float2* dst = (float2*)(sQd + r * 132 + c4 * 8);
        dst[0] = make_float2(q.x, q.x);
        dst[1] = make_float2(q.y, q.y);
        dst[2] = make_float2(q.z, q.z);
        dst[3] = make_float2(q.w, q.w);
    }

    float o[4][4];
    float mrow[4], lrow[4];
#pragma unroll
    for (int i = 0; i < 4; i++) {
        mrow[i] = -CUDART_INF_F;
        lrow[i] = 0.0f;
#pragma unroll
        for (int j = 0; j < 4; j++) o[i][j] = 0.0f;
    }

    for (int kt = 0; kt < LK_ / 128; kt++) {
        const float* kp = kptr + (size_t)kt * 128 * E_;
        const float* vp = vptr + (size_t)kt * 128 * E_;

        __syncthreads();  // previous tile's PV reads of sV/sP done

        // Load V tile [key][e]
        for (int i = tid; i < 2048; i += 512) {
            int r = i >> 4, c4 = i & 15;
            *(float4*)(sV + r * 68 + c4 * 4) = ((const float4*)(vp + r * E_))[c4];
        }
        // Load K tile transposed: sKt[e][key]
        for (int i = tid; i < 2048; i += 512) {
            int keyr = i >> 4, c4 = i & 15;
            float4 kv = ((const float4*)(kp + keyr * E_))[c4];
            sKt[(c4 * 4 + 0) * 132 + keyr] = kv.x;
            sKt[(c4 * 4 + 1) * 132 + keyr] = kv.y;
            sKt[(c4 * 4 + 2) * 132 + keyr] = kv.z;
            sKt[(c4 * 4 + 3) * 132 + keyr] = kv.w;
        }
        __syncthreads();

        // S = Q @ K^T via packed f32x2: per-thread 4 rows x 8 cols (4 pairs)
        unsigned long long s2[4][4];
#pragma unroll
        for (int i = 0; i < 4; i++)
#pragma unroll
            for (int j = 0; j < 4; j++) s2[i][j] = 0ull;

#pragma unroll 4
        for (int e = 0; e < E_; e++) {
            ulonglong2 k0 = *(const ulonglong2*)(sKt + e * 132 + tx * 4);
            ulonglong2 k1 = *(const ulonglong2*)(sKt + e * 132 + 64 + tx * 4);
#pragma unroll
            for (int i = 0; i < 4; i++) {
                unsigned long long qp =
                    *(const unsigned long long*)(sQd + (ty + 32 * i) * 132 + 2 * e);
                ffma2(s2[i][0], qp, k0.x);
                ffma2(s2[i][1], qp, k0.y);
                ffma2(s2[i][2], qp, k1.x);
                ffma2(s2[i][3], qp, k1.y);
            }
        }

        // Online softmax (row split across 16 tx lanes; xor-shfl within halves)
#pragma unroll
        for (int i = 0; i < 4; i++) {
            float2 p0 = upk2(s2[i][0]);
            float2 p1 = upk2(s2[i][1]);
            float2 p2 = upk2(s2[i][2]);
            float2 p3 = upk2(s2[i][3]);
            float v0 = p0.x, v1 = p0.y, v2 = p1.x, v3 = p1.y;
            float v4 = p2.x, v5 = p2.y, v6 = p3.x, v7 = p3.y;

            float m = fmaxf(fmaxf(fmaxf(v0, v1), fmaxf(v2, v3)),
                            fmaxf(fmaxf(v4, v5), fmaxf(v6, v7)));
#pragma unroll
            for (int off = 1; off < 16; off <<= 1)
                m = fmaxf(m, __shfl_xor_sync(0xffffffffu, m, off));
            float mnew = fmaxf(mrow[i], m);
            float corr = __expf(mrow[i] - mnew);
            mrow[i] = mnew;

            v0 = __expf(v0 - mnew); v1 = __expf(v1 - mnew);
            v2 = __expf(v2 - mnew); v3 = __expf(v3 - mnew);
            v4 = __expf(v4 - mnew); v5 = __expf(v5 - mnew);
            v6 = __expf(v6 - mnew); v7 = __expf(v7 - mnew);
            float psum = ((v0 + v1) + (v2 + v3)) + ((v4 + v5) + (v6 + v7));
#pragma unroll
            for (int off = 1; off < 16; off <<= 1)
                psum += __shfl_xor_sync(0xffffffffu, psum, off);
            lrow[i] = lrow[i] * corr + psum;
#pragma unroll
            for (int j = 0; j < 4; j++) o[i][j] *= corr;

            int row = ty + 32 * i;
            *(float4*)(sP + row * 132 + tx * 4)      = make_float4(v0, v1, v2, v3);
            *(float4*)(sP + row * 132 + 64 + tx * 4) = make_float4(v4, v5, v6, v7);
        }
        __syncthreads();  // P fully written

        // O += P @ V : per-thread 4 rows x 4 cols (scalar FFMA)
        for (int k = 0; k < 128; k += 4) {
            float4 pv[4];
#pragma unroll
            for (int i = 0; i < 4; i++)
                pv[i] = *(float4*)(sP + (ty + 32 * i) * 132 + k);
#pragma unroll
            for (int kk = 0; kk < 4; kk++) {
                float4 vv = *(float4*)(sV + (k + kk) * 68 + tx * 4);
#pragma unroll
                for (int i = 0; i < 4; i++) {
                    float p = ((const float*)&pv[i])[kk];
                    o[i][0] += p * vv.x;
                    o[i][1] += p * vv.y;
                    o[i][2] += p * vv.z;
                    o[i][3] += p * vv.w;
                }
            }
        }
    }

    // Normalize and write out
    float* op = out + ((size_t)b * LQ_ + q0) * E_;
#pragma unroll
    for (int i = 0; i < 4; i++) {
        float inv = 1.0f / lrow[i];
        float4 r4 = make_float4(o[i][0] * inv, o[i][1] * inv,
                                o[i][2] * inv, o[i][3] * inv);
        *(float4*)(op + (size_t)(ty + 32 * i) * E_ + tx * 4) = r4;
    }
}

// ---------------------------------------------------------------------------
extern "C" void kernel_launch(void* const* d_in, const int* in_sizes, int n_in,
                              void* d_out, int out_size)
{
    const float* query = (const float*)d_in[0];
    const float* key   = (const float*)d_in[1];
    const float* Wq    = (const float*)d_in[2];
    const float* Wk    = (const float*)d_in[3];
    const float* Wv    = (const float*)d_in[4];

    cudaFuncSetAttribute(proj_kernel, cudaFuncAttributeMaxDynamicSharedMemorySize,
                         PROJ_SMEM_BYTES);
    cudaFuncSetAttribute(flash_kernel, cudaFuncAttributeMaxDynamicSharedMemorySize,
                         FLASH_SMEM_BYTES);

    dim3 gp(128, 3);
    proj_kernel<<<gp, 256, PROJ_SMEM_BYTES>>>(query, key, Wq, Wk, Wv);

    dim3 gf(LQ_ / 128, B_);
    flash_kernel<<<gf, 512, FLASH_SMEM_BYTES>>>((float*)d_out);
}

// round 9
// speedup vs baseline: 2.4418x; 2.4418x over previous
#include <cuda_runtime.h>
#include <cuda_bf16.h>
#include <math_constants.h>
#include <cstdint>

#define B_  8
#define LQ_ 2048
#define LK_ 2048
#define D_  128
#define E_  64

// Projected q/k/v as bf16 hi/lo, plain row-major [B*L][64]. 2 MB each.
#define PROJ_ELEMS (B_ * LQ_ * E_)
__device__ __align__(16) unsigned char g_qh[PROJ_ELEMS * 2];
__device__ __align__(16) unsigned char g_ql[PROJ_ELEMS * 2];
__device__ __align__(16) unsigned char g_kh[PROJ_ELEMS * 2];
__device__ __align__(16) unsigned char g_kl[PROJ_ELEMS * 2];
__device__ __align__(16) unsigned char g_vh[PROJ_ELEMS * 2];
__device__ __align__(16) unsigned char g_vl[PROJ_ELEMS * 2];

// ============================ helpers ======================================
__device__ __forceinline__ uint32_t smem_u32(const void* p) {
    uint32_t a;
    asm("{ .reg .u64 t; cvta.to.shared.u64 t, %1; cvt.u32.u64 %0, t; }"
        : "=r"(a) : "l"(p));
    return a;
}
__device__ __forceinline__ unsigned pk2(float a, float b) {
    unsigned short ha = __bfloat16_as_ushort(__float2bfloat16_rn(a));
    unsigned short hb = __bfloat16_as_ushort(__float2bfloat16_rn(b));
    return ((unsigned)hb << 16) | (unsigned)ha;
}
__device__ __forceinline__ float bf16_hi(float v) {
    return __bfloat162float(__float2bfloat16_rn(v));
}

// D += A * B, m16n8k16, bf16 x bf16 -> f32
__device__ __forceinline__ void mma16816(float* d, const uint32_t* a,
                                         const uint32_t* b)
{
    asm volatile(
        "mma.sync.aligned.m16n8k16.row.col.f32.bf16.bf16.f32 "
        "{%0,%1,%2,%3}, {%4,%5,%6,%7}, {%8,%9}, {%0,%1,%2,%3};"
        : "+f"(d[0]), "+f"(d[1]), "+f"(d[2]), "+f"(d[3])
        : "r"(a[0]), "r"(a[1]), "r"(a[2]), "r"(a[3]), "r"(b[0]), "r"(b[1]));
}
__device__ __forceinline__ void ldsm4(uint32_t* r, uint32_t addr) {
    asm volatile("ldmatrix.sync.aligned.m8n8.x4.shared.b16 {%0,%1,%2,%3}, [%4];"
        : "=r"(r[0]), "=r"(r[1]), "=r"(r[2]), "=r"(r[3]) : "r"(addr));
}
__device__ __forceinline__ void ldsm2(uint32_t* r, uint32_t addr) {
    asm volatile("ldmatrix.sync.aligned.m8n8.x2.shared.b16 {%0,%1}, [%2];"
        : "=r"(r[0]), "=r"(r[1]) : "r"(addr));
}
__device__ __forceinline__ void ldsm2t(uint32_t* r, uint32_t addr) {
    asm volatile("ldmatrix.sync.aligned.m8n8.x2.trans.shared.b16 {%0,%1}, [%2];"
        : "=r"(r[0]), "=r"(r[1]) : "r"(addr));
}

// ===========================================================================
// Projection: out[row, 0:64] = X[row, 0:128] @ W[128,64], bf16 hi/lo output.
// grid (128, 3); 256 threads; thread (tx=tid&15, ty=tid>>4): 8 rows x 4 cols.
// ===========================================================================
#define PROJ_SMEM_BYTES ((128 * 132 + 128 * 68) * 4)

__global__ __launch_bounds__(256, 1) void proj_kernel(
    const float* __restrict__ query,
    const float* __restrict__ key,
    const float* __restrict__ Wq,
    const float* __restrict__ Wk,
    const float* __restrict__ Wv)
{
    extern __shared__ __align__(1024) unsigned char dynsm[];
    float* smem = (float*)dynsm;
    float* sX = smem;             // [128][132]
    float* sW = smem + 128 * 132; // [128][68]

    const float* X;
    const float* W;
    unsigned char* outh;
    unsigned char* outl;
    const int mat = blockIdx.y;
    if (mat == 0)      { X = query; W = Wq; outh = g_qh; outl = g_ql; }
    else if (mat == 1) { X = key;   W = Wk; outh = g_kh; outl = g_kl; }
    else               { X = key;   W = Wv; outh = g_vh; outl = g_vl; }

    const int tid = threadIdx.x;
    const int tx = tid & 15;
    const int ty = tid >> 4;
    const int row0 = blockIdx.x * 128;

    for (int i = tid; i < 128 * 16; i += 256) {
        int r = i >> 4, c4 = i & 15;
        *(float4*)(sW + r * 68 + c4 * 4) = ((const float4*)(W + r * 64))[c4];
    }
    for (int i = tid; i < 128 * 32; i += 256) {
        int r = i >> 5, c4 = i & 31;
        *(float4*)(sX + r * 132 + c4 * 4) =
            ((const float4*)(X + (size_t)(row0 + r) * D_))[c4];
    }
    __syncthreads();

    float acc[8][4];
#pragma unroll
    for (int i = 0; i < 8; i++)
#pragma unroll
        for (int j = 0; j < 4; j++) acc[i][j] = 0.0f;

    for (int k = 0; k < 128; k += 4) {
        float4 xv[8];
#pragma unroll
        for (int i = 0; i < 8; i++)
            xv[i] = *(float4*)(sX + (ty + 16 * i) * 132 + k);
#pragma unroll
        for (int kk = 0; kk < 4; kk++) {
            float4 wv = *(float4*)(sW + (k + kk) * 68 + tx * 4);
#pragma unroll
            for (int i = 0; i < 8; i++) {
                float a = ((const float*)&xv[i])[kk];
                acc[i][0] += a * wv.x;
                acc[i][1] += a * wv.y;
                acc[i][2] += a * wv.z;
                acc[i][3] += a * wv.w;
            }
        }
    }

#pragma unroll
    for (int i = 0; i < 8; i++) {
        size_t r = (size_t)(row0 + ty + 16 * i);
        float h0 = bf16_hi(acc[i][0]), h1 = bf16_hi(acc[i][1]);
        float h2 = bf16_hi(acc[i][2]), h3 = bf16_hi(acc[i][3]);
        uint2 wh = make_uint2(pk2(h0, h1), pk2(h2, h3));
        uint2 wl = make_uint2(pk2(acc[i][0] - h0, acc[i][1] - h1),
                              pk2(acc[i][2] - h2, acc[i][3] - h3));
        size_t byteoff = (r * 64 + tx * 4) * 2;
        *(uint2*)(outh + byteoff) = wh;
        *(uint2*)(outl + byteoff) = wl;
    }
}

// ===========================================================================
// Flash attention via mma.sync m16n8k16 bf16 (3-pass hi/lo compensation).
// grid (16, 8), 256 threads = 8 warps; warp owns 16 q-rows x all 128 keys.
// Smem tiles [128][64] bf16, rows 128B, XOR-swizzled at 16B granularity:
//   byteoff(row, chunk) = row*128 + ((chunk ^ (row&7)) << 4)
// ===========================================================================
#define SQH 0
#define SQL 16384
#define SKH 32768
#define SKL 49152
#define SVH 65536
#define SVL 81920
#define FLASH_SMEM_BYTES 98304

__global__ __launch_bounds__(256, 1) void flash_kernel(float* __restrict__ out)
{
    extern __shared__ __align__(1024) unsigned char dynsm[];
    const uint32_t sb = smem_u32(dynsm);

    const int tid = threadIdx.x;
    const int wid = tid >> 5;
    const int lane = tid & 31;
    const int gid = lane >> 2;   // group (row within 8)
    const int tig = lane & 3;    // thread-in-group (col pair)
    const int stripe = wid * 16; // this warp's 16 q-rows
    const int b = blockIdx.y;
    const int qt = blockIdx.x;

    // ---- load Q hi/lo tiles into swizzled smem (resident) ---------------
    {
        const size_t base = ((size_t)b * LQ_ + qt * 128) * 64 * 2;  // bytes
        const uint4* gh = (const uint4*)(g_qh + base);
        const uint4* gl = (const uint4*)(g_ql + base);
        uint4* dh = (uint4*)(dynsm + SQH);
        uint4* dl = (uint4*)(dynsm + SQL);
        for (int i = tid; i < 1024; i += 256) {
            int row = i >> 3, ch = i & 7;
            int d = row * 8 + (ch ^ (row & 7));
            dh[d] = gh[i];
            dl[d] = gl[i];
        }
    }

    float o[8][4];
#pragma unroll
    for (int i = 0; i < 8; i++)
#pragma unroll
        for (int j = 0; j < 4; j++) o[i][j] = 0.0f;
    float m0 = -CUDART_INF_F, m1 = -CUDART_INF_F, l0 = 0.0f, l1 = 0.0f;

    for (int kt = 0; kt < 16; kt++) {
        __syncthreads();  // previous tile's ldmatrix reads done
        // ---- load K/V hi/lo tiles -------------------------------------
        {
            const size_t base = ((size_t)b * LK_ + kt * 128) * 64 * 2;
            const uint4* kh = (const uint4*)(g_kh + base);
            const uint4* kl = (const uint4*)(g_kl + base);
            const uint4* vh = (const uint4*)(g_vh + base);
            const uint4* vl = (const uint4*)(g_vl + base);
            uint4* dkh = (uint4*)(dynsm + SKH);
            uint4* dkl = (uint4*)(dynsm + SKL);
            uint4* dvh = (uint4*)(dynsm + SVH);
            uint4* dvl = (uint4*)(dynsm + SVL);
            for (int i = tid; i < 1024; i += 256) {
                int row = i >> 3, ch = i & 7;
                int d = row * 8 + (ch ^ (row & 7));
                dkh[d] = kh[i];
                dkl[d] = kl[i];
                dvh[d] = vh[i];
                dvl[d] = vl[i];
            }
        }
        __syncthreads();

        // ---- S = Q K^T (3-pass) : c[nt] = 16x8 tile, keys nt*8..+7 ------
        float c[16][4];
#pragma unroll
        for (int nt = 0; nt < 16; nt++)
#pragma unroll
            for (int j = 0; j < 4; j++) c[nt][j] = 0.0f;

#pragma unroll
        for (int ks = 0; ks < 4; ks++) {   // e = ks*16 .. +15
            uint32_t aqh[4], aql[4];
            {
                int arow = stripe + (lane & 7) + ((lane >> 3) & 1) * 8;
                int achunk = ks * 2 + (lane >> 4);
                uint32_t aoff = (uint32_t)(arow * 128 +
                                ((achunk ^ (arow & 7)) << 4));
                ldsm4(aqh, sb + SQH + aoff);
                ldsm4(aql, sb + SQL + aoff);
            }
            int brow = (lane & 7);
            int bchunk = ks * 2 + ((lane >> 3) & 1);
#pragma unroll
            for (int nt = 0; nt < 16; nt++) {
                int row = nt * 8 + brow;
                uint32_t boff = (uint32_t)(row * 128 +
                                ((bchunk ^ (row & 7)) << 4));
                uint32_t bh[2], bl[2];
                ldsm2(bh, sb + SKH + boff);
                ldsm2(bl, sb + SKL + boff);
                mma16816(c[nt], aqh, bh);
                mma16816(c[nt], aql, bh);
                mma16816(c[nt], aqh, bl);
            }
        }

        // ---- online softmax (rows r0 = stripe+gid, r1 = r0+8) -----------
        float mx0 = -CUDART_INF_F, mx1 = -CUDART_INF_F;
#pragma unroll
        for (int nt = 0; nt < 16; nt++) {
            mx0 = fmaxf(mx0, fmaxf(c[nt][0], c[nt][1]));
            mx1 = fmaxf(mx1, fmaxf(c[nt][2], c[nt][3]));
        }
        mx0 = fmaxf(mx0, __shfl_xor_sync(0xffffffffu, mx0, 1));
        mx0 = fmaxf(mx0, __shfl_xor_sync(0xffffffffu, mx0, 2));
        mx1 = fmaxf(mx1, __shfl_xor_sync(0xffffffffu, mx1, 1));
        mx1 = fmaxf(mx1, __shfl_xor_sync(0xffffffffu, mx1, 2));

        float nm0 = fmaxf(m0, mx0), nm1 = fmaxf(m1, mx1);
        float corr0 = __expf(m0 - nm0), corr1 = __expf(m1 - nm1);
        m0 = nm0; m1 = nm1;

        float s0 = 0.0f, s1 = 0.0f;
#pragma unroll
        for (int nt = 0; nt < 16; nt++) {
            c[nt][0] = __expf(c[nt][0] - m0);
            c[nt][1] = __expf(c[nt][1] - m0);
            c[nt][2] = __expf(c[nt][2] - m1);
            c[nt][3] = __expf(c[nt][3] - m1);
            s0 += c[nt][0] + c[nt][1];
            s1 += c[nt][2] + c[nt][3];
        }
        s0 += __shfl_xor_sync(0xffffffffu, s0, 1);
        s0 += __shfl_xor_sync(0xffffffffu, s0, 2);
        s1 += __shfl_xor_sync(0xffffffffu, s1, 1);
        s1 += __shfl_xor_sync(0xffffffffu, s1, 2);
        l0 = l0 * corr0 + s0;
        l1 = l1 * corr1 + s1;

#pragma unroll
        for (int nt = 0; nt < 8; nt++) {
            o[nt][0] *= corr0; o[nt][1] *= corr0;
            o[nt][2] *= corr1; o[nt][3] *= corr1;
        }

        // ---- O += P V (3-pass); P stays in registers --------------------
#pragma unroll
        for (int ks = 0; ks < 8; ks++) {   // keys = ks*16 .. +15
            uint32_t ah[4], al[4];
            {
                float p0 = c[2 * ks][0],     p1 = c[2 * ks][1];
                float p2 = c[2 * ks][2],     p3 = c[2 * ks][3];
                float p4 = c[2 * ks + 1][0], p5 = c[2 * ks + 1][1];
                float p6 = c[2 * ks + 1][2], p7 = c[2 * ks + 1][3];
                float h0 = bf16_hi(p0), h1 = bf16_hi(p1);
                float h2 = bf16_hi(p2), h3 = bf16_hi(p3);
                float h4 = bf16_hi(p4), h5 = bf16_hi(p5);
                float h6 = bf16_hi(p6), h7 = bf16_hi(p7);
                ah[0] = pk2(h0, h1); ah[1] = pk2(h2, h3);
                ah[2] = pk2(h4, h5); ah[3] = pk2(h6, h7);
                al[0] = pk2(p0 - h0, p1 - h1); al[1] = pk2(p2 - h2, p3 - h3);
                al[2] = pk2(p4 - h4, p5 - h5); al[3] = pk2(p6 - h6, p7 - h7);
            }
            int vrow = ks * 16 + (lane & 15);
#pragma unroll
            for (int nt = 0; nt < 8; nt++) {
                uint32_t voff = (uint32_t)(vrow * 128 +
                                ((nt ^ (vrow & 7)) << 4));
                uint32_t bvh[2], bvl[2];
                ldsm2t(bvh, sb + SVH + voff);
                ldsm2t(bvl, sb + SVL + voff);
                mma16816(o[nt], ah, bvh);
                mma16816(o[nt], al, bvh);
                mma16816(o[nt], ah, bvl);
            }
        }
    }

    // ---- epilogue: O / l -> out ----------------------------------------
    {
        float inv0 = 1.0f / l0, inv1 = 1.0f / l1;
        float* op = out + ((size_t)b * LQ_ + qt * 128) * E_;
        int r0 = stripe + gid;
        int r1 = r0 + 8;
#pragma unroll
        for (int nt = 0; nt < 8; nt++) {
            int e = nt * 8 + 2 * tig;
            *(float2*)(op + (size_t)r0 * E_ + e) =
                make_float2(o[nt][0] * inv0, o[nt][1] * inv0);
            *(float2*)(op + (size_t)r1 * E_ + e) =
                make_float2(o[nt][2] * inv1, o[nt][3] * inv1);
        }
    }
}

// ---------------------------------------------------------------------------
extern "C" void kernel_launch(void* const* d_in, const int* in_sizes, int n_in,
                              void* d_out, int out_size)
{
    const float* query = (const float*)d_in[0];
    const float* key   = (const float*)d_in[1];
    const float* Wq    = (const float*)d_in[2];
    const float* Wk    = (const float*)d_in[3];
    const float* Wv    = (const float*)d_in[4];

    cudaFuncSetAttribute(proj_kernel, cudaFuncAttributeMaxDynamicSharedMemorySize,
                         PROJ_SMEM_BYTES);
    cudaFuncSetAttribute(flash_kernel, cudaFuncAttributeMaxDynamicSharedMemorySize,
                         FLASH_SMEM_BYTES);

    dim3 gp(128, 3);
    proj_kernel<<<gp, 256, PROJ_SMEM_BYTES>>>(query, key, Wq, Wk, Wv);

    dim3 gf(LQ_ / 128, B_);
    flash_kernel<<<gf, 256, FLASH_SMEM_BYTES>>>((float*)d_out);
}

// round 10
// speedup vs baseline: 2.5317x; 1.0368x over previous
#include <cuda_runtime.h>
#include <cuda_bf16.h>
#include <math_constants.h>
#include <cstdint>

#define B_  8
#define LQ_ 2048
#define LK_ 2048
#define D_  128
#define E_  64

// Projected q/k/v as bf16 hi/lo, plain row-major [B*L][64]. 2 MB each.
#define PROJ_ELEMS (B_ * LQ_ * E_)
__device__ __align__(16) unsigned char g_qh[PROJ_ELEMS * 2];
__device__ __align__(16) unsigned char g_ql[PROJ_ELEMS * 2];
__device__ __align__(16) unsigned char g_kh[PROJ_ELEMS * 2];
__device__ __align__(16) unsigned char g_kl[PROJ_ELEMS * 2];
__device__ __align__(16) unsigned char g_vh[PROJ_ELEMS * 2];
__device__ __align__(16) unsigned char g_vl[PROJ_ELEMS * 2];

// ============================ helpers ======================================
__device__ __forceinline__ uint32_t smem_u32(const void* p) {
    uint32_t a;
    asm("{ .reg .u64 t; cvta.to.shared.u64 t, %1; cvt.u32.u64 %0, t; }"
        : "=r"(a) : "l"(p));
    return a;
}
__device__ __forceinline__ unsigned pk2(float a, float b) {
    unsigned short ha = __bfloat16_as_ushort(__float2bfloat16_rn(a));
    unsigned short hb = __bfloat16_as_ushort(__float2bfloat16_rn(b));
    return ((unsigned)hb << 16) | (unsigned)ha;
}
__device__ __forceinline__ float bf16_hi(float v) {
    return __bfloat162float(__float2bfloat16_rn(v));
}

// D += A * B, m16n8k16, bf16 x bf16 -> f32
__device__ __forceinline__ void mma16816(float* d, const uint32_t* a,
                                         const uint32_t* b)
{
    asm volatile(
        "mma.sync.aligned.m16n8k16.row.col.f32.bf16.bf16.f32 "
        "{%0,%1,%2,%3}, {%4,%5,%6,%7}, {%8,%9}, {%0,%1,%2,%3};"
        : "+f"(d[0]), "+f"(d[1]), "+f"(d[2]), "+f"(d[3])
        : "r"(a[0]), "r"(a[1]), "r"(a[2]), "r"(a[3]), "r"(b[0]), "r"(b[1]));
}
__device__ __forceinline__ void ldsm4(uint32_t* r, uint32_t addr) {
    asm volatile("ldmatrix.sync.aligned.m8n8.x4.shared.b16 {%0,%1,%2,%3}, [%4];"
        : "=r"(r[0]), "=r"(r[1]), "=r"(r[2]), "=r"(r[3]) : "r"(addr));
}
__device__ __forceinline__ void ldsm2(uint32_t* r, uint32_t addr) {
    asm volatile("ldmatrix.sync.aligned.m8n8.x2.shared.b16 {%0,%1}, [%2];"
        : "=r"(r[0]), "=r"(r[1]) : "r"(addr));
}
__device__ __forceinline__ void ldsm2t(uint32_t* r, uint32_t addr) {
    asm volatile("ldmatrix.sync.aligned.m8n8.x2.trans.shared.b16 {%0,%1}, [%2];"
        : "=r"(r[0]), "=r"(r[1]) : "r"(addr));
}

// ===========================================================================
// Projection: out[row, 0:64] = X[row, 0:128] @ W[128,64], bf16 hi/lo output.
// grid (128, 3); 256 threads; thread (tx=tid&15, ty=tid>>4): 8 rows x 4 cols.
// ===========================================================================
#define PROJ_SMEM_BYTES ((128 * 132 + 128 * 68) * 4)

__global__ __launch_bounds__(256, 1) void proj_kernel(
    const float* __restrict__ query,
    const float* __restrict__ key,
    const float* __restrict__ Wq,
    const float* __restrict__ Wk,
    const float* __restrict__ Wv)
{
    extern __shared__ __align__(1024) unsigned char dynsm[];
    float* smem = (float*)dynsm;
    float* sX = smem;             // [128][132]
    float* sW = smem + 128 * 132; // [128][68]

    const float* X;
    const float* W;
    unsigned char* outh;
    unsigned char* outl;
    const int mat = blockIdx.y;
    if (mat == 0)      { X = query; W = Wq; outh = g_qh; outl = g_ql; }
    else if (mat == 1) { X = key;   W = Wk; outh = g_kh; outl = g_kl; }
    else               { X = key;   W = Wv; outh = g_vh; outl = g_vl; }

    const int tid = threadIdx.x;
    const int tx = tid & 15;
    const int ty = tid >> 4;
    const int row0 = blockIdx.x * 128;

    for (int i = tid; i < 128 * 16; i += 256) {
        int r = i >> 4, c4 = i & 15;
        *(float4*)(sW + r * 68 + c4 * 4) = ((const float4*)(W + r * 64))[c4];
    }
    for (int i = tid; i < 128 * 32; i += 256) {
        int r = i >> 5, c4 = i & 31;
        *(float4*)(sX + r * 132 + c4 * 4) =
            ((const float4*)(X + (size_t)(row0 + r) * D_))[c4];
    }
    __syncthreads();

    float acc[8][4];
#pragma unroll
    for (int i = 0; i < 8; i++)
#pragma unroll
        for (int j = 0; j < 4; j++) acc[i][j] = 0.0f;

    for (int k = 0; k < 128; k += 4) {
        float4 xv[8];
#pragma unroll
        for (int i = 0; i < 8; i++)
            xv[i] = *(float4*)(sX + (ty + 16 * i) * 132 + k);
#pragma unroll
        for (int kk = 0; kk < 4; kk++) {
            float4 wv = *(float4*)(sW + (k + kk) * 68 + tx * 4);
#pragma unroll
            for (int i = 0; i < 8; i++) {
                float a = ((const float*)&xv[i])[kk];
                acc[i][0] += a * wv.x;
                acc[i][1] += a * wv.y;
                acc[i][2] += a * wv.z;
                acc[i][3] += a * wv.w;
            }
        }
    }

#pragma unroll
    for (int i = 0; i < 8; i++) {
        size_t r = (size_t)(row0 + ty + 16 * i);
        float h0 = bf16_hi(acc[i][0]), h1 = bf16_hi(acc[i][1]);
        float h2 = bf16_hi(acc[i][2]), h3 = bf16_hi(acc[i][3]);
        uint2 wh = make_uint2(pk2(h0, h1), pk2(h2, h3));
        uint2 wl = make_uint2(pk2(acc[i][0] - h0, acc[i][1] - h1),
                              pk2(acc[i][2] - h2, acc[i][3] - h3));
        size_t byteoff = (r * 64 + tx * 4) * 2;
        *(uint2*)(outh + byteoff) = wh;
        *(uint2*)(outl + byteoff) = wl;
    }
}

// ===========================================================================
// Flash attention via mma.sync m16n8k16 bf16 (3-pass hi/lo compensation).
// grid (16, 8), 512 threads = 16 warps. Warp (rw = wid&7, half = wid>>3):
// 16 q-rows (rw*16..+15) x 64 keys (half*64..+63). Warp pairs (rw, 0/1)
// share row softmax stats via smem and sum partial O in the epilogue.
// Smem tiles [128][64] bf16, rows 128B, XOR-swizzled at 16B granularity:
//   byteoff(row, chunk) = row*128 + ((chunk ^ (row&7)) << 4)
// ===========================================================================
#define SQH 0
#define SQL 16384
#define SKH 32768
#define SKL 49152
#define SVH 65536
#define SVL 81920
#define SRED 98304                       // sRedM[2][128], sRedS[2][128]
#define FLASH_SMEM_BYTES (98304 + 2048)

__global__ __launch_bounds__(512, 1) void flash_kernel(float* __restrict__ out)
{
    extern __shared__ __align__(1024) unsigned char dynsm[];
    const uint32_t sb = smem_u32(dynsm);

    const int tid = threadIdx.x;
    const int wid = tid >> 5;
    const int lane = tid & 31;
    const int gid = lane >> 2;    // row group within 8
    const int tig = lane & 3;     // col pair
    const int rw = wid & 7;
    const int half = wid >> 3;
    const int stripe = rw * 16;   // this warp's q-rows
    const int kbase = half * 64;  // this warp's keys
    const int b = blockIdx.y;
    const int qt = blockIdx.x;
    const int r0 = stripe + gid;
    const int r1 = r0 + 8;

    float* sRedM = (float*)(dynsm + SRED);   // [2][128]
    float* sRedS = sRedM + 256;              // [2][128]

    // ---- load Q hi/lo tiles into swizzled smem (resident) ---------------
    {
        const size_t base = ((size_t)b * LQ_ + qt * 128) * 64 * 2;  // bytes
        const uint4* gh = (const uint4*)(g_qh + base);
        const uint4* gl = (const uint4*)(g_ql + base);
        uint4* dh = (uint4*)(dynsm + SQH);
        uint4* dl = (uint4*)(dynsm + SQL);
        for (int i = tid; i < 1024; i += 512) {
            int row = i >> 3, ch = i & 7;
            int d = row * 8 + (ch ^ (row & 7));
            dh[d] = gh[i];
            dl[d] = gl[i];
        }
    }

    float o[8][4];
#pragma unroll
    for (int i = 0; i < 8; i++)
#pragma unroll
        for (int j = 0; j < 4; j++) o[i][j] = 0.0f;
    float m0 = -CUDART_INF_F, m1 = -CUDART_INF_F, l0 = 0.0f, l1 = 0.0f;

    for (int kt = 0; kt < 16; kt++) {
        __syncthreads();  // previous tile's ldmatrix reads done
        // ---- load K/V hi/lo tiles -------------------------------------
        {
            const size_t base = ((size_t)b * LK_ + kt * 128) * 64 * 2;
            const uint4* kh = (const uint4*)(g_kh + base);
            const uint4* kl = (const uint4*)(g_kl + base);
            const uint4* vh = (const uint4*)(g_vh + base);
            const uint4* vl = (const uint4*)(g_vl + base);
            uint4* dkh = (uint4*)(dynsm + SKH);
            uint4* dkl = (uint4*)(dynsm + SKL);
            uint4* dvh = (uint4*)(dynsm + SVH);
            uint4* dvl = (uint4*)(dynsm + SVL);
            for (int i = tid; i < 1024; i += 512) {
                int row = i >> 3, ch = i & 7;
                int d = row * 8 + (ch ^ (row & 7));
                dkh[d] = kh[i];
                dkl[d] = kl[i];
                dvh[d] = vh[i];
                dvl[d] = vl[i];
            }
        }
        __syncthreads();

        // ---- S = Q K^T (3-pass) : c[nt] = 16x8, keys kbase + nt*8..+7 ---
        float c[8][4];
#pragma unroll
        for (int nt = 0; nt < 8; nt++)
#pragma unroll
            for (int j = 0; j < 4; j++) c[nt][j] = 0.0f;

#pragma unroll
        for (int ks = 0; ks < 4; ks++) {   // e = ks*16 .. +15
            uint32_t aqh[4], aql[4];
            {
                int arow = stripe + (lane & 7) + ((lane >> 3) & 1) * 8;
                int achunk = ks * 2 + (lane >> 4);
                uint32_t aoff = (uint32_t)(arow * 128 +
                                ((achunk ^ (arow & 7)) << 4));
                ldsm4(aqh, sb + SQH + aoff);
                ldsm4(aql, sb + SQL + aoff);
            }
            int brow = (lane & 7);
            int bchunk = ks * 2 + ((lane >> 3) & 1);
#pragma unroll
            for (int nt = 0; nt < 8; nt++) {
                int row = kbase + nt * 8 + brow;
                uint32_t boff = (uint32_t)(row * 128 +
                                ((bchunk ^ (row & 7)) << 4));
                uint32_t bh[2], bl[2];
                ldsm2(bh, sb + SKH + boff);
                ldsm2(bl, sb + SKL + boff);
                mma16816(c[nt], aqh, bh);
                mma16816(c[nt], aql, bh);
                mma16816(c[nt], aqh, bl);
            }
        }

        // ---- online softmax (pair-combined via smem) --------------------
        float mx0 = -CUDART_INF_F, mx1 = -CUDART_INF_F;
#pragma unroll
        for (int nt = 0; nt < 8; nt++) {
            mx0 = fmaxf(mx0, fmaxf(c[nt][0], c[nt][1]));
            mx1 = fmaxf(mx1, fmaxf(c[nt][2], c[nt][3]));
        }
        mx0 = fmaxf(mx0, __shfl_xor_sync(0xffffffffu, mx0, 1));
        mx0 = fmaxf(mx0, __shfl_xor_sync(0xffffffffu, mx0, 2));
        mx1 = fmaxf(mx1, __shfl_xor_sync(0xffffffffu, mx1, 1));
        mx1 = fmaxf(mx1, __shfl_xor_sync(0xffffffffu, mx1, 2));
        if (tig == 0) {
            sRedM[half * 128 + r0] = mx0;
            sRedM[half * 128 + r1] = mx1;
        }
        __syncthreads();
        float gmx0 = fmaxf(sRedM[r0], sRedM[128 + r0]);
        float gmx1 = fmaxf(sRedM[r1], sRedM[128 + r1]);

        float nm0 = fmaxf(m0, gmx0), nm1 = fmaxf(m1, gmx1);
        float corr0 = __expf(m0 - nm0), corr1 = __expf(m1 - nm1);
        m0 = nm0; m1 = nm1;

        float s0 = 0.0f, s1 = 0.0f;
#pragma unroll
        for (int nt = 0; nt < 8; nt++) {
            c[nt][0] = __expf(c[nt][0] - m0);
            c[nt][1] = __expf(c[nt][1] - m0);
            c[nt][2] = __expf(c[nt][2] - m1);
            c[nt][3] = __expf(c[nt][3] - m1);
            s0 += c[nt][0] + c[nt][1];
            s1 += c[nt][2] + c[nt][3];
        }
        s0 += __shfl_xor_sync(0xffffffffu, s0, 1);
        s0 += __shfl_xor_sync(0xffffffffu, s0, 2);
        s1 += __shfl_xor_sync(0xffffffffu, s1, 1);
        s1 += __shfl_xor_sync(0xffffffffu, s1, 2);
        if (tig == 0) {
            sRedS[half * 128 + r0] = s0;
            sRedS[half * 128 + r1] = s1;
        }
        __syncthreads();
        l0 = l0 * corr0 + sRedS[r0] + sRedS[128 + r0];
        l1 = l1 * corr1 + sRedS[r1] + sRedS[128 + r1];

#pragma unroll
        for (int nt = 0; nt < 8; nt++) {
            o[nt][0] *= corr0; o[nt][1] *= corr0;
            o[nt][2] *= corr1; o[nt][3] *= corr1;
        }

        // ---- O += P V (3-pass); P stays in registers --------------------
#pragma unroll
        for (int ks = 0; ks < 4; ks++) {   // keys = kbase + ks*16 .. +15
            uint32_t ah[4], al[4];
            {
                float p0 = c[2 * ks][0],     p1 = c[2 * ks][1];
                float p2 = c[2 * ks][2],     p3 = c[2 * ks][3];
                float p4 = c[2 * ks + 1][0], p5 = c[2 * ks + 1][1];
                float p6 = c[2 * ks + 1][2], p7 = c[2 * ks + 1][3];
                float h0 = bf16_hi(p0), h1 = bf16_hi(p1);
                float h2 = bf16_hi(p2), h3 = bf16_hi(p3);
                float h4 = bf16_hi(p4), h5 = bf16_hi(p5);
                float h6 = bf16_hi(p6), h7 = bf16_hi(p7);
                ah[0] = pk2(h0, h1); ah[1] = pk2(h2, h3);
                ah[2] = pk2(h4, h5); ah[3] = pk2(h6, h7);
                al[0] = pk2(p0 - h0, p1 - h1); al[1] = pk2(p2 - h2, p3 - h3);
                al[2] = pk2(p4 - h4, p5 - h5); al[3] = pk2(p6 - h6, p7 - h7);
            }
            int vrow = kbase + ks * 16 + (lane & 15);
#pragma unroll
            for (int nt = 0; nt < 8; nt++) {
                uint32_t voff = (uint32_t)(vrow * 128 +
                                ((nt ^ (vrow & 7)) << 4));
                uint32_t bvh[2], bvl[2];
                ldsm2t(bvh, sb + SVH + voff);
                ldsm2t(bvl, sb + SVL + voff);
                mma16816(o[nt], ah, bvh);
                mma16816(o[nt], al, bvh);
                mma16816(o[nt], ah, bvl);
            }
        }
    }

    // ---- epilogue: combine warp-pair partial O, normalize, write --------
    __syncthreads();  // all smem tile reads done; reuse Q region as sO
    float* sO = (float*)dynsm;  // [128][64]
    if (half == 1) {
#pragma unroll
        for (int nt = 0; nt < 8; nt++) {
            int e = nt * 8 + 2 * tig;
            *(float2*)(sO + r0 * 64 + e) = make_float2(o[nt][0], o[nt][1]);
            *(float2*)(sO + r1 * 64 + e) = make_float2(o[nt][2], o[nt][3]);
        }
    }
    __syncthreads();
    if (half == 0) {
        float inv0 = 1.0f / l0, inv1 = 1.0f / l1;
        float* op = out + ((size_t)b * LQ_ + qt * 128) * E_;
#pragma unroll
        for (int nt = 0; nt < 8; nt++) {
            int e = nt * 8 + 2 * tig;
            float2 p0 = *(float2*)(sO + r0 * 64 + e);
            float2 p1 = *(float2*)(sO + r1 * 64 + e);
            *(float2*)(op + (size_t)r0 * E_ + e) =
                make_float2((o[nt][0] + p0.x) * inv0, (o[nt][1] + p0.y) * inv0);
            *(float2*)(op + (size_t)r1 * E_ + e) =
                make_float2((o[nt][2] + p1.x) * inv1, (o[nt][3] + p1.y) * inv1);
        }
    }
}

// ---------------------------------------------------------------------------
extern "C" void kernel_launch(void* const* d_in, const int* in_sizes, int n_in,
                              void* d_out, int out_size)
{
    const float* query = (const float*)d_in[0];
    const float* key   = (const float*)d_in[1];
    const float* Wq    = (const float*)d_in[2];
    const float* Wk    = (const float*)d_in[3];
    const float* Wv    = (const float*)d_in[4];

    cudaFuncSetAttribute(proj_kernel, cudaFuncAttributeMaxDynamicSharedMemorySize,
                         PROJ_SMEM_BYTES);
    cudaFuncSetAttribute(flash_kernel, cudaFuncAttributeMaxDynamicSharedMemorySize,
                         FLASH_SMEM_BYTES);

    dim3 gp(128, 3);
    proj_kernel<<<gp, 256, PROJ_SMEM_BYTES>>>(query, key, Wq, Wk, Wv);

    dim3 gf(LQ_ / 128, B_);
    flash_kernel<<<gf, 512, FLASH_SMEM_BYTES>>>((float*)d_out);
}

// round 11
// speedup vs baseline: 2.5559x; 1.0095x over previous
#include <cuda_runtime.h>
#include <cuda_bf16.h>
#include <math_constants.h>
#include <cstdint>

#define B_  8
#define LQ_ 2048
#define LK_ 2048
#define D_  128
#define E_  64

// Projected q/k/v as bf16 hi/lo, plain row-major [B*L][64]. 2 MB each.
#define PROJ_ELEMS (B_ * LQ_ * E_)
__device__ __align__(16) unsigned char g_qh[PROJ_ELEMS * 2];
__device__ __align__(16) unsigned char g_ql[PROJ_ELEMS * 2];
__device__ __align__(16) unsigned char g_kh[PROJ_ELEMS * 2];
__device__ __align__(16) unsigned char g_kl[PROJ_ELEMS * 2];
__device__ __align__(16) unsigned char g_vh[PROJ_ELEMS * 2];
__device__ __align__(16) unsigned char g_vl[PROJ_ELEMS * 2];

// ============================ helpers ======================================
__device__ __forceinline__ uint32_t smem_u32(const void* p) {
    uint32_t a;
    asm("{ .reg .u64 t; cvta.to.shared.u64 t, %1; cvt.u32.u64 %0, t; }"
        : "=r"(a) : "l"(p));
    return a;
}
__device__ __forceinline__ unsigned pk2(float a, float b) {
    unsigned short ha = __bfloat16_as_ushort(__float2bfloat16_rn(a));
    unsigned short hb = __bfloat16_as_ushort(__float2bfloat16_rn(b));
    return ((unsigned)hb << 16) | (unsigned)ha;
}
__device__ __forceinline__ float bf16_hi(float v) {
    return __bfloat162float(__float2bfloat16_rn(v));
}

// D += A * B, m16n8k16, bf16 x bf16 -> f32
__device__ __forceinline__ void mma16816(float* d, const uint32_t* a,
                                         const uint32_t* b)
{
    asm volatile(
        "mma.sync.aligned.m16n8k16.row.col.f32.bf16.bf16.f32 "
        "{%0,%1,%2,%3}, {%4,%5,%6,%7}, {%8,%9}, {%0,%1,%2,%3};"
        : "+f"(d[0]), "+f"(d[1]), "+f"(d[2]), "+f"(d[3])
        : "r"(a[0]), "r"(a[1]), "r"(a[2]), "r"(a[3]), "r"(b[0]), "r"(b[1]));
}
__device__ __forceinline__ void ldsm4(uint32_t* r, uint32_t addr) {
    asm volatile("ldmatrix.sync.aligned.m8n8.x4.shared.b16 {%0,%1,%2,%3}, [%4];"
        : "=r"(r[0]), "=r"(r[1]), "=r"(r[2]), "=r"(r[3]) : "r"(addr));
}
__device__ __forceinline__ void ldsm4t(uint32_t* r, uint32_t addr) {
    asm volatile("ldmatrix.sync.aligned.m8n8.x4.trans.shared.b16 {%0,%1,%2,%3}, [%4];"
        : "=r"(r[0]), "=r"(r[1]), "=r"(r[2]), "=r"(r[3]) : "r"(addr));
}

// ===========================================================================
// Projection: out[row, 0:64] = X[row, 0:128] @ W[128,64], bf16 hi/lo output.
// grid (128, 3); 256 threads; thread (tx=tid&15, ty=tid>>4): 8 rows x 4 cols.
// ===========================================================================
#define PROJ_SMEM_BYTES ((128 * 132 + 128 * 68) * 4)

__global__ __launch_bounds__(256, 1) void proj_kernel(
    const float* __restrict__ query,
    const float* __restrict__ key,
    const float* __restrict__ Wq,
    const float* __restrict__ Wk,
    const float* __restrict__ Wv)
{
    extern __shared__ __align__(1024) unsigned char dynsm[];
    float* smem = (float*)dynsm;
    float* sX = smem;             // [128][132]
    float* sW = smem + 128 * 132; // [128][68]

    const float* X;
    const float* W;
    unsigned char* outh;
    unsigned char* outl;
    const int mat = blockIdx.y;
    if (mat == 0)      { X = query; W = Wq; outh = g_qh; outl = g_ql; }
    else if (mat == 1) { X = key;   W = Wk; outh = g_kh; outl = g_kl; }
    else               { X = key;   W = Wv; outh = g_vh; outl = g_vl; }

    const int tid = threadIdx.x;
    const int tx = tid & 15;
    const int ty = tid >> 4;
    const int row0 = blockIdx.x * 128;

    for (int i = tid; i < 128 * 16; i += 256) {
        int r = i >> 4, c4 = i & 15;
        *(float4*)(sW + r * 68 + c4 * 4) = ((const float4*)(W + r * 64))[c4];
    }
    for (int i = tid; i < 128 * 32; i += 256) {
        int r = i >> 5, c4 = i & 31;
        *(float4*)(sX + r * 132 + c4 * 4) =
            ((const float4*)(X + (size_t)(row0 + r) * D_))[c4];
    }
    __syncthreads();

    float acc[8][4];
#pragma unroll
    for (int i = 0; i < 8; i++)
#pragma unroll
        for (int j = 0; j < 4; j++) acc[i][j] = 0.0f;

    for (int k = 0; k < 128; k += 4) {
        float4 xv[8];
#pragma unroll
        for (int i = 0; i < 8; i++)
            xv[i] = *(float4*)(sX + (ty + 16 * i) * 132 + k);
#pragma unroll
        for (int kk = 0; kk < 4; kk++) {
            float4 wv = *(float4*)(sW + (k + kk) * 68 + tx * 4);
#pragma unroll
            for (int i = 0; i < 8; i++) {
                float a = ((const float*)&xv[i])[kk];
                acc[i][0] += a * wv.x;
                acc[i][1] += a * wv.y;
                acc[i][2] += a * wv.z;
                acc[i][3] += a * wv.w;
            }
        }
    }

#pragma unroll
    for (int i = 0; i < 8; i++) {
        size_t r = (size_t)(row0 + ty + 16 * i);
        float h0 = bf16_hi(acc[i][0]), h1 = bf16_hi(acc[i][1]);
        float h2 = bf16_hi(acc[i][2]), h3 = bf16_hi(acc[i][3]);
        uint2 wh = make_uint2(pk2(h0, h1), pk2(h2, h3));
        uint2 wl = make_uint2(pk2(acc[i][0] - h0, acc[i][1] - h1),
                              pk2(acc[i][2] - h2, acc[i][3] - h3));
        size_t byteoff = (r * 64 + tx * 4) * 2;
        *(uint2*)(outh + byteoff) = wh;
        *(uint2*)(outl + byteoff) = wl;
    }
}

// ===========================================================================
// Flash attention via mma.sync m16n8k16 bf16 (3-pass hi/lo compensation),
// dependency-interleaved: per k-step, all 8 B-fragments are loaded first
// (x4 ldmatrix pairs), then each pass sweeps nt=0..7 so consecutive MMAs hit
// different accumulators (chain distance 8 >= HMMA latency).
// grid (16, 8), 512 threads = 16 warps. Warp (rw = wid&7, half = wid>>3):
// 16 q-rows (rw*16..+15) x 64 keys (half*64..+63).
// Smem tiles [128][64] bf16, rows 128B, XOR-swizzled at 16B granularity:
//   byteoff(row, chunk) = row*128 + ((chunk ^ (row&7)) << 4)
// ===========================================================================
#define SQH 0
#define SQL 16384
#define SKH 32768
#define SKL 49152
#define SVH 65536
#define SVL 81920
#define SRED 98304                       // sRedM[2][128], sRedS[2][128]
#define FLASH_SMEM_BYTES (98304 + 2048)

__global__ __launch_bounds__(512, 1) void flash_kernel(float* __restrict__ out)
{
    extern __shared__ __align__(1024) unsigned char dynsm[];
    const uint32_t sb = smem_u32(dynsm);

    const int tid = threadIdx.x;
    const int wid = tid >> 5;
    const int lane = tid & 31;
    const int gid = lane >> 2;    // row group within 8
    const int tig = lane & 3;     // col pair
    const int rw = wid & 7;
    const int half = wid >> 3;
    const int stripe = rw * 16;   // this warp's q-rows
    const int kbase = half * 64;  // this warp's keys
    const int b = blockIdx.y;
    const int qt = blockIdx.x;
    const int r0 = stripe + gid;
    const int r1 = r0 + 8;

    float* sRedM = (float*)(dynsm + SRED);   // [2][128]
    float* sRedS = sRedM + 256;              // [2][128]

    // ---- load Q hi/lo tiles into swizzled smem (resident) ---------------
    {
        const size_t base = ((size_t)b * LQ_ + qt * 128) * 64 * 2;  // bytes
        const uint4* gh = (const uint4*)(g_qh + base);
        const uint4* gl = (const uint4*)(g_ql + base);
        uint4* dh = (uint4*)(dynsm + SQH);
        uint4* dl = (uint4*)(dynsm + SQL);
        for (int i = tid; i < 1024; i += 512) {
            int row = i >> 3, ch = i & 7;
            int d = row * 8 + (ch ^ (row & 7));
            dh[d] = gh[i];
            dl[d] = gl[i];
        }
    }

    float o[8][4];
#pragma unroll
    for (int i = 0; i < 8; i++)
#pragma unroll
        for (int j = 0; j < 4; j++) o[i][j] = 0.0f;
    float m0 = -CUDART_INF_F, m1 = -CUDART_INF_F, l0 = 0.0f, l1 = 0.0f;

    for (int kt = 0; kt < 16; kt++) {
        __syncthreads();  // previous tile's ldmatrix reads done
        // ---- load K/V hi/lo tiles -------------------------------------
        {
            const size_t base = ((size_t)b * LK_ + kt * 128) * 64 * 2;
            const uint4* kh = (const uint4*)(g_kh + base);
            const uint4* kl = (const uint4*)(g_kl + base);
            const uint4* vh = (const uint4*)(g_vh + base);
            const uint4* vl = (const uint4*)(g_vl + base);
            uint4* dkh = (uint4*)(dynsm + SKH);
            uint4* dkl = (uint4*)(dynsm + SKL);
            uint4* dvh = (uint4*)(dynsm + SVH);
            uint4* dvl = (uint4*)(dynsm + SVL);
            for (int i = tid; i < 1024; i += 512) {
                int row = i >> 3, ch = i & 7;
                int d = row * 8 + (ch ^ (row & 7));
                dkh[d] = kh[i];
                dkl[d] = kl[i];
                dvh[d] = vh[i];
                dvl[d] = vl[i];
            }
        }
        __syncthreads();

        // ---- S = Q K^T (3-pass, interleaved) ----------------------------
        float c[8][4];
#pragma unroll
        for (int nt = 0; nt < 8; nt++)
#pragma unroll
            for (int j = 0; j < 4; j++) c[nt][j] = 0.0f;

#pragma unroll
        for (int ks = 0; ks < 4; ks++) {   // e = ks*16 .. +15
            uint32_t aqh[4], aql[4];
            {
                int arow = stripe + (lane & 7) + ((lane >> 3) & 1) * 8;
                int achunk = ks * 2 + (lane >> 4);
                uint32_t aoff = (uint32_t)(arow * 128 +
                                ((achunk ^ (arow & 7)) << 4));
                ldsm4(aqh, sb + SQH + aoff);
                ldsm4(aql, sb + SQL + aoff);
            }
            // B addresses: x4 loads fragments for nt pair (np*2, np*2+1):
            // matrix idx = lane>>3: nt = np*2 + (lane>>4), chunk sel (lane>>3)&1
            const int brow = lane & 7;
            const int bchunk = ks * 2 + ((lane >> 3) & 1);
            const int bsel = lane >> 4;
            uint32_t bf[8][2];
            uint32_t boffs[4];
#pragma unroll
            for (int np = 0; np < 4; np++) {
                int row = kbase + (np * 2 + bsel) * 8 + brow;
                boffs[np] = (uint32_t)(row * 128 + ((bchunk ^ (row & 7)) << 4));
                uint32_t t[4];
                ldsm4(t, sb + SKH + boffs[np]);
                bf[np * 2][0] = t[0]; bf[np * 2][1] = t[1];
                bf[np * 2 + 1][0] = t[2]; bf[np * 2 + 1][1] = t[3];
            }
#pragma unroll
            for (int nt = 0; nt < 8; nt++) mma16816(c[nt], aqh, bf[nt]);
#pragma unroll
            for (int nt = 0; nt < 8; nt++) mma16816(c[nt], aql, bf[nt]);
            // reload lo K fragments into the same registers
#pragma unroll
            for (int np = 0; np < 4; np++) {
                uint32_t t[4];
                ldsm4(t, sb + SKL + boffs[np]);
                bf[np * 2][0] = t[0]; bf[np * 2][1] = t[1];
                bf[np * 2 + 1][0] = t[2]; bf[np * 2 + 1][1] = t[3];
            }
#pragma unroll
            for (int nt = 0; nt < 8; nt++) mma16816(c[nt], aqh, bf[nt]);
        }

        // ---- online softmax (pair-combined via smem) --------------------
        float mx0 = -CUDART_INF_F, mx1 = -CUDART_INF_F;
#pragma unroll
        for (int nt = 0; nt < 8; nt++) {
            mx0 = fmaxf(mx0, fmaxf(c[nt][0], c[nt][1]));
            mx1 = fmaxf(mx1, fmaxf(c[nt][2], c[nt][3]));
        }
        mx0 = fmaxf(mx0, __shfl_xor_sync(0xffffffffu, mx0, 1));
        mx0 = fmaxf(mx0, __shfl_xor_sync(0xffffffffu, mx0, 2));
        mx1 = fmaxf(mx1, __shfl_xor_sync(0xffffffffu, mx1, 1));
        mx1 = fmaxf(mx1, __shfl_xor_sync(0xffffffffu, mx1, 2));
        if (tig == 0) {
            sRedM[half * 128 + r0] = mx0;
            sRedM[half * 128 + r1] = mx1;
        }
        __syncthreads();
        float gmx0 = fmaxf(sRedM[r0], sRedM[128 + r0]);
        float gmx1 = fmaxf(sRedM[r1], sRedM[128 + r1]);

        float nm0 = fmaxf(m0, gmx0), nm1 = fmaxf(m1, gmx1);
        float corr0 = __expf(m0 - nm0), corr1 = __expf(m1 - nm1);
        m0 = nm0; m1 = nm1;

        float s0 = 0.0f, s1 = 0.0f;
#pragma unroll
        for (int nt = 0; nt < 8; nt++) {
            c[nt][0] = __expf(c[nt][0] - m0);
            c[nt][1] = __expf(c[nt][1] - m0);
            c[nt][2] = __expf(c[nt][2] - m1);
            c[nt][3] = __expf(c[nt][3] - m1);
            s0 += c[nt][0] + c[nt][1];
            s1 += c[nt][2] + c[nt][3];
        }
        s0 += __shfl_xor_sync(0xffffffffu, s0, 1);
        s0 += __shfl_xor_sync(0xffffffffu, s0, 2);
        s1 += __shfl_xor_sync(0xffffffffu, s1, 1);
        s1 += __shfl_xor_sync(0xffffffffu, s1, 2);
        if (tig == 0) {
            sRedS[half * 128 + r0] = s0;
            sRedS[half * 128 + r1] = s1;
        }
        __syncthreads();
        l0 = l0 * corr0 + sRedS[r0] + sRedS[128 + r0];
        l1 = l1 * corr1 + sRedS[r1] + sRedS[128 + r1];

#pragma unroll
        for (int nt = 0; nt < 8; nt++) {
            o[nt][0] *= corr0; o[nt][1] *= corr0;
            o[nt][2] *= corr1; o[nt][3] *= corr1;
        }

        // ---- O += P V (3-pass, interleaved); P stays in registers -------
#pragma unroll
        for (int ks = 0; ks < 4; ks++) {   // keys = kbase + ks*16 .. +15
            uint32_t ah[4], al[4];
            {
                float p0 = c[2 * ks][0],     p1 = c[2 * ks][1];
                float p2 = c[2 * ks][2],     p3 = c[2 * ks][3];
                float p4 = c[2 * ks + 1][0], p5 = c[2 * ks + 1][1];
                float p6 = c[2 * ks + 1][2], p7 = c[2 * ks + 1][3];
                float h0 = bf16_hi(p0), h1 = bf16_hi(p1);
                float h2 = bf16_hi(p2), h3 = bf16_hi(p3);
                float h4 = bf16_hi(p4), h5 = bf16_hi(p5);
                float h6 = bf16_hi(p6), h7 = bf16_hi(p7);
                ah[0] = pk2(h0, h1); ah[1] = pk2(h2, h3);
                ah[2] = pk2(h4, h5); ah[3] = pk2(h6, h7);
                al[0] = pk2(p0 - h0, p1 - h1); al[1] = pk2(p2 - h2, p3 - h3);
                al[2] = pk2(p4 - h4, p5 - h5); al[3] = pk2(p6 - h6, p7 - h7);
            }
            // V fragments: x4.trans loads chunk pair (np*2 + (lane>>4))
            const int vrow = kbase + ks * 16 + (lane & 15);
            const int vsel = lane >> 4;
            uint32_t bv[8][2];
            uint32_t voffs[4];
#pragma unroll
            for (int np = 0; np < 4; np++) {
                int chunk = np * 2 + vsel;
                voffs[np] = (uint32_t)(vrow * 128 + ((chunk ^ (vrow & 7)) << 4));
                uint32_t t[4];
                ldsm4t(t, sb + SVH + voffs[np]);
                bv[np * 2][0] = t[0]; bv[np * 2][1] = t[1];
                bv[np * 2 + 1][0] = t[2]; bv[np * 2 + 1][1] = t[3];
            }
#pragma unroll
            for (int nt = 0; nt < 8; nt++) mma16816(o[nt], ah, bv[nt]);
#pragma unroll
            for (int nt = 0; nt < 8; nt++) mma16816(o[nt], al, bv[nt]);
#pragma unroll
            for (int np = 0; np < 4; np++) {
                uint32_t t[4];
                ldsm4t(t, sb + SVL + voffs[np]);
                bv[np * 2][0] = t[0]; bv[np * 2][1] = t[1];
                bv[np * 2 + 1][0] = t[2]; bv[np * 2 + 1][1] = t[3];
            }
#pragma unroll
            for (int nt = 0; nt < 8; nt++) mma16816(o[nt], ah, bv[nt]);
        }
    }

    // ---- epilogue: combine warp-pair partial O, normalize, write --------
    __syncthreads();  // all smem tile reads done; reuse Q region as sO
    float* sO = (float*)dynsm;  // [128][64]
    if (half == 1) {
#pragma unroll
        for (int nt = 0; nt < 8; nt++) {
            int e = nt * 8 + 2 * tig;
            *(float2*)(sO + r0 * 64 + e) = make_float2(o[nt][0], o[nt][1]);
            *(float2*)(sO + r1 * 64 + e) = make_float2(o[nt][2], o[nt][3]);
        }
    }
    __syncthreads();
    if (half == 0) {
        float inv0 = 1.0f / l0, inv1 = 1.0f / l1;
        float* op = out + ((size_t)b * LQ_ + qt * 128) * E_;
#pragma unroll
        for (int nt = 0; nt < 8; nt++) {
            int e = nt * 8 + 2 * tig;
            float2 p0 = *(float2*)(sO + r0 * 64 + e);
            float2 p1 = *(float2*)(sO + r1 * 64 + e);
            *(float2*)(op + (size_t)r0 * E_ + e) =
                make_float2((o[nt][0] + p0.x) * inv0, (o[nt][1] + p0.y) * inv0);
            *(float2*)(op + (size_t)r1 * E_ + e) =
                make_float2((o[nt][2] + p1.x) * inv1, (o[nt][3] + p1.y) * inv1);
        }
    }
}

// ---------------------------------------------------------------------------
extern "C" void kernel_launch(void* const* d_in, const int* in_sizes, int n_in,
                              void* d_out, int out_size)
{
    const float* query = (const float*)d_in[0];
    const float* key   = (const float*)d_in[1];
    const float* Wq    = (const float*)d_in[2];
    const float* Wk    = (const float*)d_in[3];
    const float* Wv    = (const float*)d_in[4];

    cudaFuncSetAttribute(proj_kernel, cudaFuncAttributeMaxDynamicSharedMemorySize,
                         PROJ_SMEM_BYTES);
    cudaFuncSetAttribute(flash_kernel, cudaFuncAttributeMaxDynamicSharedMemorySize,
                         FLASH_SMEM_BYTES);

    dim3 gp(128, 3);
    proj_kernel<<<gp, 256, PROJ_SMEM_BYTES>>>(query, key, Wq, Wk, Wv);

    dim3 gf(LQ_ / 128, B_);
    flash_kernel<<<gf, 512, FLASH_SMEM_BYTES>>>((float*)d_out);
}

// round 12
// speedup vs baseline: 2.7641x; 1.0815x over previous
#include <cuda_runtime.h>
#include <cuda_bf16.h>
#include <math_constants.h>
#include <cstdint>

#define B_  8
#define LQ_ 2048
#define LK_ 2048
#define D_  128
#define E_  64

// Projected q/k/v as bf16 hi/lo, plain row-major [B*L][64]. 2 MB each.
#define PROJ_ELEMS (B_ * LQ_ * E_)
__device__ __align__(16) unsigned char g_qh[PROJ_ELEMS * 2];
__device__ __align__(16) unsigned char g_ql[PROJ_ELEMS * 2];
__device__ __align__(16) unsigned char g_kh[PROJ_ELEMS * 2];
__device__ __align__(16) unsigned char g_kl[PROJ_ELEMS * 2];
__device__ __align__(16) unsigned char g_vh[PROJ_ELEMS * 2];
__device__ __align__(16) unsigned char g_vl[PROJ_ELEMS * 2];

// ============================ helpers ======================================
__device__ __forceinline__ uint32_t smem_u32(const void* p) {
    uint32_t a;
    asm("{ .reg .u64 t; cvta.to.shared.u64 t, %1; cvt.u32.u64 %0, t; }"
        : "=r"(a) : "l"(p));
    return a;
}
__device__ __forceinline__ unsigned pk2(float a, float b) {
    unsigned short ha = __bfloat16_as_ushort(__float2bfloat16_rn(a));
    unsigned short hb = __bfloat16_as_ushort(__float2bfloat16_rn(b));
    return ((unsigned)hb << 16) | (unsigned)ha;
}
__device__ __forceinline__ float bf16_hi(float v) {
    return __bfloat162float(__float2bfloat16_rn(v));
}

// D += A * B, m16n8k16, bf16 x bf16 -> f32
__device__ __forceinline__ void mma16816(float* d, const uint32_t* a,
                                         const uint32_t* b)
{
    asm volatile(
        "mma.sync.aligned.m16n8k16.row.col.f32.bf16.bf16.f32 "
        "{%0,%1,%2,%3}, {%4,%5,%6,%7}, {%8,%9}, {%0,%1,%2,%3};"
        : "+f"(d[0]), "+f"(d[1]), "+f"(d[2]), "+f"(d[3])
        : "r"(a[0]), "r"(a[1]), "r"(a[2]), "r"(a[3]), "r"(b[0]), "r"(b[1]));
}
__device__ __forceinline__ void ldsm4(uint32_t* r, uint32_t addr) {
    asm volatile("ldmatrix.sync.aligned.m8n8.x4.shared.b16 {%0,%1,%2,%3}, [%4];"
        : "=r"(r[0]), "=r"(r[1]), "=r"(r[2]), "=r"(r[3]) : "r"(addr));
}
__device__ __forceinline__ void ldsm4t(uint32_t* r, uint32_t addr) {
    asm volatile("ldmatrix.sync.aligned.m8n8.x4.trans.shared.b16 {%0,%1,%2,%3}, [%4];"
        : "=r"(r[0]), "=r"(r[1]), "=r"(r[2]), "=r"(r[3]) : "r"(addr));
}

// ===========================================================================
// Projection via 3-pass bf16 HMMA: out[row, 0:64] = X[row, 0:128] @ W[128,64].
// grid (128, 3): x = 128-row tile, y selects (q | k | v). 256 threads, 8 warps.
// Smem: Xh/Xl [128 rows][128 cols bf16] (256B rows), Wth/Wtl [64 n][128 k]
// (256B rows). XOR swizzle at 16B granularity: off = row*256 + ((ch^(row&7))<<4).
// Warp wid: 16 rows (wid*16..+15) x all 64 out cols.
// ===========================================================================
#define PXH 0
#define PXL 32768
#define PWH 65536
#define PWL 81920
#define PROJ_SMEM_BYTES 98304

__global__ __launch_bounds__(256, 1) void proj_kernel(
    const float* __restrict__ query,
    const float* __restrict__ key,
    const float* __restrict__ Wq,
    const float* __restrict__ Wk,
    const float* __restrict__ Wv)
{
    extern __shared__ __align__(1024) unsigned char dynsm[];
    const uint32_t sb = smem_u32(dynsm);

    const float* X;
    const float* W;
    unsigned char* outh;
    unsigned char* outl;
    const int mat = blockIdx.y;
    if (mat == 0)      { X = query; W = Wq; outh = g_qh; outl = g_ql; }
    else if (mat == 1) { X = key;   W = Wk; outh = g_kh; outl = g_kl; }
    else               { X = key;   W = Wv; outh = g_vh; outl = g_vl; }

    const int tid = threadIdx.x;
    const int wid = tid >> 5;
    const int lane = tid & 31;
    const int gid = lane >> 2;
    const int tig = lane & 3;
    const int stripe = wid * 16;
    const int row0 = blockIdx.x * 128;

    // ---- split X tile into bf16 hi/lo, swizzled ------------------------
    for (int u = tid; u < 2048; u += 256) {       // (row, ch): 128 x 16
        int row = u >> 4, ch = u & 15;
        const float4* src = (const float4*)(X + (size_t)(row0 + row) * D_ + ch * 8);
        float4 a = src[0], bq = src[1];
        float h0 = bf16_hi(a.x), h1 = bf16_hi(a.y);
        float h2 = bf16_hi(a.z), h3 = bf16_hi(a.w);
        float h4 = bf16_hi(bq.x), h5 = bf16_hi(bq.y);
        float h6 = bf16_hi(bq.z), h7 = bf16_hi(bq.w);
        uint4 wh = make_uint4(pk2(h0, h1), pk2(h2, h3), pk2(h4, h5), pk2(h6, h7));
        uint4 wl = make_uint4(pk2(a.x - h0, a.y - h1), pk2(a.z - h2, a.w - h3),
                              pk2(bq.x - h4, bq.y - h5), pk2(bq.z - h6, bq.w - h7));
        uint32_t off = (uint32_t)(row * 256 + ((ch ^ (row & 7)) << 4));
        *(uint4*)(dynsm + PXH + off) = wh;
        *(uint4*)(dynsm + PXL + off) = wl;
    }
    // ---- split W^T into bf16 hi/lo, swizzled ---------------------------
    for (int u = tid; u < 1024; u += 256) {       // (n, ch): 64 x 16
        int n = u & 63, ch = u >> 6;
        float v[8];
#pragma unroll
        for (int t = 0; t < 8; t++) v[t] = W[(ch * 8 + t) * 64 + n];
        float h[8];
#pragma unroll
        for (int t = 0; t < 8; t++) h[t] = bf16_hi(v[t]);
        uint4 wh = make_uint4(pk2(h[0], h[1]), pk2(h[2], h[3]),
                              pk2(h[4], h[5]), pk2(h[6], h[7]));
        uint4 wl = make_uint4(pk2(v[0] - h[0], v[1] - h[1]),
                              pk2(v[2] - h[2], v[3] - h[3]),
                              pk2(v[4] - h[4], v[5] - h[5]),
                              pk2(v[6] - h[6], v[7] - h[7]));
        uint32_t off = (uint32_t)(n * 256 + ((ch ^ (n & 7)) << 4));
        *(uint4*)(dynsm + PWH + off) = wh;
        *(uint4*)(dynsm + PWL + off) = wl;
    }
    __syncthreads();

    // ---- 3-pass HMMA: c = Xh*Wh + Xl*Wh + Xh*Wl ------------------------
    float c[8][4];
#pragma unroll
    for (int nt = 0; nt < 8; nt++)
#pragma unroll
        for (int j = 0; j < 4; j++) c[nt][j] = 0.0f;

#pragma unroll
    for (int ks = 0; ks < 8; ks++) {   // k = ks*16 .. +15
        uint32_t axh[4], axl[4];
        {
            int arow = stripe + (lane & 7) + ((lane >> 3) & 1) * 8;
            int achunk = ks * 2 + (lane >> 4);
            uint32_t aoff = (uint32_t)(arow * 256 + ((achunk ^ (arow & 7)) << 4));
            ldsm4(axh, sb + PXH + aoff);
            ldsm4(axl, sb + PXL + aoff);
        }
        const int brow7 = lane & 7;
        const int bchunk = ks * 2 + ((lane >> 3) & 1);
        const int bsel = lane >> 4;
        uint32_t bf[8][2];
        uint32_t boffs[4];
#pragma unroll
        for (int np = 0; np < 4; np++) {
            int n = (np * 2 + bsel) * 8 + brow7;
            boffs[np] = (uint32_t)(n * 256 + ((bchunk ^ (n & 7)) << 4));
            uint32_t t[4];
            ldsm4(t, sb + PWH + boffs[np]);
            bf[np * 2][0] = t[0]; bf[np * 2][1] = t[1];
            bf[np * 2 + 1][0] = t[2]; bf[np * 2 + 1][1] = t[3];
        }
#pragma unroll
        for (int nt = 0; nt < 8; nt++) mma16816(c[nt], axh, bf[nt]);
#pragma unroll
        for (int nt = 0; nt < 8; nt++) mma16816(c[nt], axl, bf[nt]);
#pragma unroll
        for (int np = 0; np < 4; np++) {
            uint32_t t[4];
            ldsm4(t, sb + PWL + boffs[np]);
            bf[np * 2][0] = t[0]; bf[np * 2][1] = t[1];
            bf[np * 2 + 1][0] = t[2]; bf[np * 2 + 1][1] = t[3];
        }
#pragma unroll
        for (int nt = 0; nt < 8; nt++) mma16816(c[nt], axh, bf[nt]);
    }

    // ---- epilogue: split fp32 result into bf16 hi/lo, row-major --------
    {
        int r0 = row0 + stripe + gid;
        int r1 = r0 + 8;
#pragma unroll
        for (int nt = 0; nt < 8; nt++) {
            int col = nt * 8 + 2 * tig;
            float h0 = bf16_hi(c[nt][0]), h1 = bf16_hi(c[nt][1]);
            float h2 = bf16_hi(c[nt][2]), h3 = bf16_hi(c[nt][3]);
            size_t o0 = ((size_t)r0 * 64 + col) * 2;
            size_t o1 = ((size_t)r1 * 64 + col) * 2;
            *(unsigned*)(outh + o0) = pk2(h0, h1);
            *(unsigned*)(outl + o0) = pk2(c[nt][0] - h0, c[nt][1] - h1);
            *(unsigned*)(outh + o1) = pk2(h2, h3);
            *(unsigned*)(outl + o1) = pk2(c[nt][2] - h2, c[nt][3] - h3);
        }
    }
}

// ===========================================================================
// Flash attention via mma.sync m16n8k16 bf16 (3-pass hi/lo compensation).
// Unchanged from the passing R11 kernel (at its HMMA throughput floor).
// grid (16, 8), 512 threads = 16 warps. Warp (rw = wid&7, half = wid>>3):
// 16 q-rows (rw*16..+15) x 64 keys (half*64..+63).
// Smem tiles [128][64] bf16, rows 128B, XOR-swizzled at 16B granularity.
// ===========================================================================
#define SQH 0
#define SQL 16384
#define SKH 32768
#define SKL 49152
#define SVH 65536
#define SVL 81920
#define SRED 98304                       // sRedM[2][128], sRedS[2][128]
#define FLASH_SMEM_BYTES (98304 + 2048)

__global__ __launch_bounds__(512, 1) void flash_kernel(float* __restrict__ out)
{
    extern __shared__ __align__(1024) unsigned char dynsm[];
    const uint32_t sb = smem_u32(dynsm);

    const int tid = threadIdx.x;
    const int wid = tid >> 5;
    const int lane = tid & 31;
    const int gid = lane >> 2;    // row group within 8
    const int tig = lane & 3;     // col pair
    const int rw = wid & 7;
    const int half = wid >> 3;
    const int stripe = rw * 16;   // this warp's q-rows
    const int kbase = half * 64;  // this warp's keys
    const int b = blockIdx.y;
    const int qt = blockIdx.x;
    const int r0 = stripe + gid;
    const int r1 = r0 + 8;

    float* sRedM = (float*)(dynsm + SRED);   // [2][128]
    float* sRedS = sRedM + 256;              // [2][128]

    // ---- load Q hi/lo tiles into swizzled smem (resident) ---------------
    {
        const size_t base = ((size_t)b * LQ_ + qt * 128) * 64 * 2;  // bytes
        const uint4* gh = (const uint4*)(g_qh + base);
        const uint4* gl = (const uint4*)(g_ql + base);
        uint4* dh = (uint4*)(dynsm + SQH);
        uint4* dl = (uint4*)(dynsm + SQL);
        for (int i = tid; i < 1024; i += 512) {
            int row = i >> 3, ch = i & 7;
            int d = row * 8 + (ch ^ (row & 7));
            dh[d] = gh[i];
            dl[d] = gl[i];
        }
    }

    float o[8][4];
#pragma unroll
    for (int i = 0; i < 8; i++)
#pragma unroll
        for (int j = 0; j < 4; j++) o[i][j] = 0.0f;
    float m0 = -CUDART_INF_F, m1 = -CUDART_INF_F, l0 = 0.0f, l1 = 0.0f;

    for (int kt = 0; kt < 16; kt++) {
        __syncthreads();  // previous tile's ldmatrix reads done
        // ---- load K/V hi/lo tiles -------------------------------------
        {
            const size_t base = ((size_t)b * LK_ + kt * 128) * 64 * 2;
            const uint4* kh = (const uint4*)(g_kh + base);
            const uint4* kl = (const uint4*)(g_kl + base);
            const uint4* vh = (const uint4*)(g_vh + base);
            const uint4* vl = (const uint4*)(g_vl + base);
            uint4* dkh = (uint4*)(dynsm + SKH);
            uint4* dkl = (uint4*)(dynsm + SKL);
            uint4* dvh = (uint4*)(dynsm + SVH);
            uint4* dvl = (uint4*)(dynsm + SVL);
            for (int i = tid; i < 1024; i += 512) {
                int row = i >> 3, ch = i & 7;
                int d = row * 8 + (ch ^ (row & 7));
                dkh[d] = kh[i];
                dkl[d] = kl[i];
                dvh[d] = vh[i];
                dvl[d] = vl[i];
            }
        }
        __syncthreads();

        // ---- S = Q K^T (3-pass, interleaved) ----------------------------
        float c[8][4];
#pragma unroll
        for (int nt = 0; nt < 8; nt++)
#pragma unroll
            for (int j = 0; j < 4; j++) c[nt][j] = 0.0f;

#pragma unroll
        for (int ks = 0; ks < 4; ks++) {   // e = ks*16 .. +15
            uint32_t aqh[4], aql[4];
            {
                int arow = stripe + (lane & 7) + ((lane >> 3) & 1) * 8;
                int achunk = ks * 2 + (lane >> 4);
                uint32_t aoff = (uint32_t)(arow * 128 +
                                ((achunk ^ (arow & 7)) << 4));
                ldsm4(aqh, sb + SQH + aoff);
                ldsm4(aql, sb + SQL + aoff);
            }
            const int brow = lane & 7;
            const int bchunk = ks * 2 + ((lane >> 3) & 1);
            const int bsel = lane >> 4;
            uint32_t bf[8][2];
            uint32_t boffs[4];
#pragma unroll
            for (int np = 0; np < 4; np++) {
                int row = kbase + (np * 2 + bsel) * 8 + brow;
                boffs[np] = (uint32_t)(row * 128 + ((bchunk ^ (row & 7)) << 4));
                uint32_t t[4];
                ldsm4(t, sb + SKH + boffs[np]);
                bf[np * 2][0] = t[0]; bf[np * 2][1] = t[1];
                bf[np * 2 + 1][0] = t[2]; bf[np * 2 + 1][1] = t[3];
            }
#pragma unroll
            for (int nt = 0; nt < 8; nt++) mma16816(c[nt], aqh, bf[nt]);
#pragma unroll
            for (int nt = 0; nt < 8; nt++) mma16816(c[nt], aql, bf[nt]);
#pragma unroll
            for (int np = 0; np < 4; np++) {
                uint32_t t[4];
                ldsm4(t, sb + SKL + boffs[np]);
                bf[np * 2][0] = t[0]; bf[np * 2][1] = t[1];
                bf[np * 2 + 1][0] = t[2]; bf[np * 2 + 1][1] = t[3];
            }
#pragma unroll
            for (int nt = 0; nt < 8; nt++) mma16816(c[nt], aqh, bf[nt]);
        }

        // ---- online softmax (pair-combined via smem) --------------------
        float mx0 = -CUDART_INF_F, mx1 = -CUDART_INF_F;
#pragma unroll
        for (int nt = 0; nt < 8; nt++) {
            mx0 = fmaxf(mx0, fmaxf(c[nt][0], c[nt][1]));
            mx1 = fmaxf(mx1, fmaxf(c[nt][2], c[nt][3]));
        }
        mx0 = fmaxf(mx0, __shfl_xor_sync(0xffffffffu, mx0, 1));
        mx0 = fmaxf(mx0, __shfl_xor_sync(0xffffffffu, mx0, 2));
        mx1 = fmaxf(mx1, __shfl_xor_sync(0xffffffffu, mx1, 1));
        mx1 = fmaxf(mx1, __shfl_xor_sync(0xffffffffu, mx1, 2));
        if (tig == 0) {
            sRedM[half * 128 + r0] = mx0;
            sRedM[half * 128 + r1] = mx1;
        }
        __syncthreads();
        float gmx0 = fmaxf(sRedM[r0], sRedM[128 + r0]);
        float gmx1 = fmaxf(sRedM[r1], sRedM[128 + r1]);

        float nm0 = fmaxf(m0, gmx0), nm1 = fmaxf(m1, gmx1);
        float corr0 = __expf(m0 - nm0), corr1 = __expf(m1 - nm1);
        m0 = nm0; m1 = nm1;

        float s0 = 0.0f, s1 = 0.0f;
#pragma unroll
        for (int nt = 0; nt < 8; nt++) {
            c[nt][0] = __expf(c[nt][0] - m0);
            c[nt][1] = __expf(c[nt][1] - m0);
            c[nt][2] = __expf(c[nt][2] - m1);
            c[nt][3] = __expf(c[nt][3] - m1);
            s0 += c[nt][0] + c[nt][1];
            s1 += c[nt][2] + c[nt][3];
        }
        s0 += __shfl_xor_sync(0xffffffffu, s0, 1);
        s0 += __shfl_xor_sync(0xffffffffu, s0, 2);
        s1 += __shfl_xor_sync(0xffffffffu, s1, 1);
        s1 += __shfl_xor_sync(0xffffffffu, s1, 2);
        if (tig == 0) {
            sRedS[half * 128 + r0] = s0;
            sRedS[half * 128 + r1] = s1;
        }
        __syncthreads();
        l0 = l0 * corr0 + sRedS[r0] + sRedS[128 + r0];
        l1 = l1 * corr1 + sRedS[r1] + sRedS[128 + r1];

#pragma unroll
        for (int nt = 0; nt < 8; nt++) {
            o[nt][0] *= corr0; o[nt][1] *= corr0;
            o[nt][2] *= corr1; o[nt][3] *= corr1;
        }

        // ---- O += P V (3-pass, interleaved); P stays in registers -------
#pragma unroll
        for (int ks = 0; ks < 4; ks++) {   // keys = kbase + ks*16 .. +15
            uint32_t ah[4], al[4];
            {
                float p0 = c[2 * ks][0],     p1 = c[2 * ks][1];
                float p2 = c[2 * ks][2],     p3 = c[2 * ks][3];
                float p4 = c[2 * ks + 1][0], p5 = c[2 * ks + 1][1];
                float p6 = c[2 * ks + 1][2], p7 = c[2 * ks + 1][3];
                float h0 = bf16_hi(p0), h1 = bf16_hi(p1);
                float h2 = bf16_hi(p2), h3 = bf16_hi(p3);
                float h4 = bf16_hi(p4), h5 = bf16_hi(p5);
                float h6 = bf16_hi(p6), h7 = bf16_hi(p7);
                ah[0] = pk2(h0, h1); ah[1] = pk2(h2, h3);
                ah[2] = pk2(h4, h5); ah[3] = pk2(h6, h7);
                al[0] = pk2(p0 - h0, p1 - h1); al[1] = pk2(p2 - h2, p3 - h3);
                al[2] = pk2(p4 - h4, p5 - h5); al[3] = pk2(p6 - h6, p7 - h7);
            }
            const int vrow = kbase + ks * 16 + (lane & 15);
            const int vsel = lane >> 4;
            uint32_t bv[8][2];
            uint32_t voffs[4];
#pragma unroll
            for (int np = 0; np < 4; np++) {
                int chunk = np * 2 + vsel;
                voffs[np] = (uint32_t)(vrow * 128 + ((chunk ^ (vrow & 7)) << 4));
                uint32_t t[4];
                ldsm4t(t, sb + SVH + voffs[np]);
                bv[np * 2][0] = t[0]; bv[np * 2][1] = t[1];
                bv[np * 2 + 1][0] = t[2]; bv[np * 2 + 1][1] = t[3];
            }
#pragma unroll
            for (int nt = 0; nt < 8; nt++) mma16816(o[nt], ah, bv[nt]);
#pragma unroll
            for (int nt = 0; nt < 8; nt++) mma16816(o[nt], al, bv[nt]);
#pragma unroll
            for (int np = 0; np < 4; np++) {
                uint32_t t[4];
                ldsm4t(t, sb + SVL + voffs[np]);
                bv[np * 2][0] = t[0]; bv[np * 2][1] = t[1];
                bv[np * 2 + 1][0] = t[2]; bv[np * 2 + 1][1] = t[3];
            }
#pragma unroll
            for (int nt = 0; nt < 8; nt++) mma16816(o[nt], ah, bv[nt]);
        }
    }

    // ---- epilogue: combine warp-pair partial O, normalize, write --------
    __syncthreads();  // all smem tile reads done; reuse Q region as sO
    float* sO = (float*)dynsm;  // [128][64]
    if (half == 1) {
#pragma unroll
        for (int nt = 0; nt < 8; nt++) {
            int e = nt * 8 + 2 * tig;
            *(float2*)(sO + r0 * 64 + e) = make_float2(o[nt][0], o[nt][1]);
            *(float2*)(sO + r1 * 64 + e) = make_float2(o[nt][2], o[nt][3]);
        }
    }
    __syncthreads();
    if (half == 0) {
        float inv0 = 1.0f / l0, inv1 = 1.0f / l1;
        float* op = out + ((size_t)b * LQ_ + qt * 128) * E_;
#pragma unroll
        for (int nt = 0; nt < 8; nt++) {
            int e = nt * 8 + 2 * tig;
            float2 p0 = *(float2*)(sO + r0 * 64 + e);
            float2 p1 = *(float2*)(sO + r1 * 64 + e);
            *(float2*)(op + (size_t)r0 * E_ + e) =
                make_float2((o[nt][0] + p0.x) * inv0, (o[nt][1] + p0.y) * inv0);
            *(float2*)(op + (size_t)r1 * E_ + e) =
                make_float2((o[nt][2] + p1.x) * inv1, (o[nt][3] + p1.y) * inv1);
        }
    }
}

// ---------------------------------------------------------------------------
extern "C" void kernel_launch(void* const* d_in, const int* in_sizes, int n_in,
                              void* d_out, int out_size)
{
    const float* query = (const float*)d_in[0];
    const float* key   = (const float*)d_in[1];
    const float* Wq    = (const float*)d_in[2];
    const float* Wk    = (const float*)d_in[3];
    const float* Wv    = (const float*)d_in[4];

    cudaFuncSetAttribute(proj_kernel, cudaFuncAttributeMaxDynamicSharedMemorySize,
                         PROJ_SMEM_BYTES);
    cudaFuncSetAttribute(flash_kernel, cudaFuncAttributeMaxDynamicSharedMemorySize,
                         FLASH_SMEM_BYTES);

    dim3 gp(128, 3);
    proj_kernel<<<gp, 256, PROJ_SMEM_BYTES>>>(query, key, Wq, Wk, Wv);

    dim3 gf(LQ_ / 128, B_);
    flash_kernel<<<gf, 512, FLASH_SMEM_BYTES>>>((float*)d_out);
}

// round 13
// speedup vs baseline: 3.2977x; 1.1931x over previous
#include <cuda_runtime.h>
#include <cuda_fp16.h>
#include <math_constants.h>
#include <cstdint>

#define B_  8
#define LQ_ 2048
#define LK_ 2048
#define D_  128
#define E_  64

// Projected q/k/v as fp16 hi/lo, plain row-major [B*L][64]. 2 MB each.
#define PROJ_ELEMS (B_ * LQ_ * E_)
__device__ __align__(16) unsigned char g_qh[PROJ_ELEMS * 2];
__device__ __align__(16) unsigned char g_ql[PROJ_ELEMS * 2];
__device__ __align__(16) unsigned char g_kh[PROJ_ELEMS * 2];
__device__ __align__(16) unsigned char g_kl[PROJ_ELEMS * 2];
__device__ __align__(16) unsigned char g_vh[PROJ_ELEMS * 2];
__device__ __align__(16) unsigned char g_vl[PROJ_ELEMS * 2];

// ============================ helpers ======================================
__device__ __forceinline__ uint32_t smem_u32(const void* p) {
    uint32_t a;
    asm("{ .reg .u64 t; cvta.to.shared.u64 t, %1; cvt.u32.u64 %0, t; }"
        : "=r"(a) : "l"(p));
    return a;
}
__device__ __forceinline__ unsigned pk2h(float a, float b) {
    __half2 h = __floats2half2_rn(a, b);
    return *reinterpret_cast<unsigned*>(&h);
}
__device__ __forceinline__ float f16_hi(float v) {
    return __half2float(__float2half_rn(v));
}

// D += A * B, m16n8k16, fp16 x fp16 -> f32
__device__ __forceinline__ void mma16816(float* d, const uint32_t* a,
                                         const uint32_t* b)
{
    asm volatile(
        "mma.sync.aligned.m16n8k16.row.col.f32.f16.f16.f32 "
        "{%0,%1,%2,%3}, {%4,%5,%6,%7}, {%8,%9}, {%0,%1,%2,%3};"
        : "+f"(d[0]), "+f"(d[1]), "+f"(d[2]), "+f"(d[3])
        : "r"(a[0]), "r"(a[1]), "r"(a[2]), "r"(a[3]), "r"(b[0]), "r"(b[1]));
}
__device__ __forceinline__ void ldsm4(uint32_t* r, uint32_t addr) {
    asm volatile("ldmatrix.sync.aligned.m8n8.x4.shared.b16 {%0,%1,%2,%3}, [%4];"
        : "=r"(r[0]), "=r"(r[1]), "=r"(r[2]), "=r"(r[3]) : "r"(addr));
}
__device__ __forceinline__ void ldsm4t(uint32_t* r, uint32_t addr) {
    asm volatile("ldmatrix.sync.aligned.m8n8.x4.trans.shared.b16 {%0,%1,%2,%3}, [%4];"
        : "=r"(r[0]), "=r"(r[1]), "=r"(r[2]), "=r"(r[3]) : "r"(addr));
}

// ===========================================================================
// Projection via 3-pass fp16 HMMA: out[row, 0:64] = X[row, 0:128] @ W[128,64].
// grid (128, 3): x = 128-row tile, y selects (q | k | v). 256 threads, 8 warps.
// Smem: Xh/Xl [128 rows][128 cols fp16] (256B rows), Wth/Wtl [64 n][128 k]
// (256B rows). XOR swizzle at 16B granularity: off = row*256 + ((ch^(row&7))<<4).
// Warp wid: 16 rows (wid*16..+15) x all 64 out cols.
// ===========================================================================
#define PXH 0
#define PXL 32768
#define PWH 65536
#define PWL 81920
#define PROJ_SMEM_BYTES 98304

__global__ __launch_bounds__(256, 1) void proj_kernel(
    const float* __restrict__ query,
    const float* __restrict__ key,
    const float* __restrict__ Wq,
    const float* __restrict__ Wk,
    const float* __restrict__ Wv)
{
    extern __shared__ __align__(1024) unsigned char dynsm[];
    const uint32_t sb = smem_u32(dynsm);

    const float* X;
    const float* W;
    unsigned char* outh;
    unsigned char* outl;
    const int mat = blockIdx.y;
    if (mat == 0)      { X = query; W = Wq; outh = g_qh; outl = g_ql; }
    else if (mat == 1) { X = key;   W = Wk; outh = g_kh; outl = g_kl; }
    else               { X = key;   W = Wv; outh = g_vh; outl = g_vl; }

    const int tid = threadIdx.x;
    const int wid = tid >> 5;
    const int lane = tid & 31;
    const int gid = lane >> 2;
    const int tig = lane & 3;
    const int stripe = wid * 16;
    const int row0 = blockIdx.x * 128;

    // ---- split X tile into fp16 hi/lo, swizzled ------------------------
    for (int u = tid; u < 2048; u += 256) {       // (row, ch): 128 x 16
        int row = u >> 4, ch = u & 15;
        const float4* src = (const float4*)(X + (size_t)(row0 + row) * D_ + ch * 8);
        float4 a = src[0], bq = src[1];
        float h0 = f16_hi(a.x), h1 = f16_hi(a.y);
        float h2 = f16_hi(a.z), h3 = f16_hi(a.w);
        float h4 = f16_hi(bq.x), h5 = f16_hi(bq.y);
        float h6 = f16_hi(bq.z), h7 = f16_hi(bq.w);
        uint4 wh = make_uint4(pk2h(h0, h1), pk2h(h2, h3), pk2h(h4, h5), pk2h(h6, h7));
        uint4 wl = make_uint4(pk2h(a.x - h0, a.y - h1), pk2h(a.z - h2, a.w - h3),
                              pk2h(bq.x - h4, bq.y - h5), pk2h(bq.z - h6, bq.w - h7));
        uint32_t off = (uint32_t)(row * 256 + ((ch ^ (row & 7)) << 4));
        *(uint4*)(dynsm + PXH + off) = wh;
        *(uint4*)(dynsm + PXL + off) = wl;
    }
    // ---- split W^T into fp16 hi/lo, swizzled ---------------------------
    for (int u = tid; u < 1024; u += 256) {       // (n, ch): 64 x 16
        int n = u & 63, ch = u >> 6;
        float v[8];
#pragma unroll
        for (int t = 0; t < 8; t++) v[t] = W[(ch * 8 + t) * 64 + n];
        float h[8];
#pragma unroll
        for (int t = 0; t < 8; t++) h[t] = f16_hi(v[t]);
        uint4 wh = make_uint4(pk2h(h[0], h[1]), pk2h(h[2], h[3]),
                              pk2h(h[4], h[5]), pk2h(h[6], h[7]));
        uint4 wl = make_uint4(pk2h(v[0] - h[0], v[1] - h[1]),
                              pk2h(v[2] - h[2], v[3] - h[3]),
                              pk2h(v[4] - h[4], v[5] - h[5]),
                              pk2h(v[6] - h[6], v[7] - h[7]));
        uint32_t off = (uint32_t)(n * 256 + ((ch ^ (n & 7)) << 4));
        *(uint4*)(dynsm + PWH + off) = wh;
        *(uint4*)(dynsm + PWL + off) = wl;
    }
    __syncthreads();

    // ---- 3-pass HMMA: c = Xh*Wh + Xl*Wh + Xh*Wl ------------------------
    float c[8][4];
#pragma unroll
    for (int nt = 0; nt < 8; nt++)
#pragma unroll
        for (int j = 0; j < 4; j++) c[nt][j] = 0.0f;

#pragma unroll
    for (int ks = 0; ks < 8; ks++) {   // k = ks*16 .. +15
        uint32_t axh[4], axl[4];
        {
            int arow = stripe + (lane & 7) + ((lane >> 3) & 1) * 8;
            int achunk = ks * 2 + (lane >> 4);
            uint32_t aoff = (uint32_t)(arow * 256 + ((achunk ^ (arow & 7)) << 4));
            ldsm4(axh, sb + PXH + aoff);
            ldsm4(axl, sb + PXL + aoff);
        }
        const int brow7 = lane & 7;
        const int bchunk = ks * 2 + ((lane >> 3) & 1);
        const int bsel = lane >> 4;
        uint32_t bf[8][2];
        uint32_t boffs[4];
#pragma unroll
        for (int np = 0; np < 4; np++) {
            int n = (np * 2 + bsel) * 8 + brow7;
            boffs[np] = (uint32_t)(n * 256 + ((bchunk ^ (n & 7)) << 4));
            uint32_t t[4];
            ldsm4(t, sb + PWH + boffs[np]);
            bf[np * 2][0] = t[0]; bf[np * 2][1] = t[1];
            bf[np * 2 + 1][0] = t[2]; bf[np * 2 + 1][1] = t[3];
        }
#pragma unroll
        for (int nt = 0; nt < 8; nt++) mma16816(c[nt], axh, bf[nt]);
#pragma unroll
        for (int nt = 0; nt < 8; nt++) mma16816(c[nt], axl, bf[nt]);
#pragma unroll
        for (int np = 0; np < 4; np++) {
            uint32_t t[4];
            ldsm4(t, sb + PWL + boffs[np]);
            bf[np * 2][0] = t[0]; bf[np * 2][1] = t[1];
            bf[np * 2 + 1][0] = t[2]; bf[np * 2 + 1][1] = t[3];
        }
#pragma unroll
        for (int nt = 0; nt < 8; nt++) mma16816(c[nt], axh, bf[nt]);
    }

    // ---- epilogue: split fp32 result into fp16 hi/lo, row-major --------
    {
        int r0 = row0 + stripe + gid;
        int r1 = r0 + 8;
#pragma unroll
        for (int nt = 0; nt < 8; nt++) {
            int col = nt * 8 + 2 * tig;
            float h0 = f16_hi(c[nt][0]), h1 = f16_hi(c[nt][1]);
            float h2 = f16_hi(c[nt][2]), h3 = f16_hi(c[nt][3]);
            size_t o0 = ((size_t)r0 * 64 + col) * 2;
            size_t o1 = ((size_t)r1 * 64 + col) * 2;
            *(unsigned*)(outh + o0) = pk2h(h0, h1);
            *(unsigned*)(outl + o0) = pk2h(c[nt][0] - h0, c[nt][1] - h1);
            *(unsigned*)(outh + o1) = pk2h(h2, h3);
            *(unsigned*)(outl + o1) = pk2h(c[nt][2] - h2, c[nt][3] - h3);
        }
    }
}

// ===========================================================================
// Flash attention via mma.sync m16n8k16 fp16.
// QK: 3-pass hi/lo compensation (Qh*Kh + Ql*Kh + Qh*Kl).
// PV: 2-pass — P as single fp16 (quant error ~1.4e-4), V split hi/lo.
// grid (16, 8), 512 threads = 16 warps. Warp (rw = wid&7, half = wid>>3):
// 16 q-rows (rw*16..+15) x 64 keys (half*64..+63).
// Smem tiles [128][64] fp16, rows 128B, XOR-swizzled at 16B granularity.
// ===========================================================================
#define SQH 0
#define SQL 16384
#define SKH 32768
#define SKL 49152
#define SVH 65536
#define SVL 81920
#define SRED 98304                       // sRedM[2][128], sRedS[2][128]
#define FLASH_SMEM_BYTES (98304 + 2048)

__global__ __launch_bounds__(512, 1) void flash_kernel(float* __restrict__ out)
{
    extern __shared__ __align__(1024) unsigned char dynsm[];
    const uint32_t sb = smem_u32(dynsm);

    const int tid = threadIdx.x;
    const int wid = tid >> 5;
    const int lane = tid & 31;
    const int gid = lane >> 2;    // row group within 8
    const int tig = lane & 3;     // col pair
    const int rw = wid & 7;
    const int half = wid >> 3;
    const int stripe = rw * 16;   // this warp's q-rows
    const int kbase = half * 64;  // this warp's keys
    const int b = blockIdx.y;
    const int qt = blockIdx.x;
    const int r0 = stripe + gid;
    const int r1 = r0 + 8;

    float* sRedM = (float*)(dynsm + SRED);   // [2][128]
    float* sRedS = sRedM + 256;              // [2][128]

    // ---- load Q hi/lo tiles into swizzled smem (resident) ---------------
    {
        const size_t base = ((size_t)b * LQ_ + qt * 128) * 64 * 2;  // bytes
        const uint4* gh = (const uint4*)(g_qh + base);
        const uint4* gl = (const uint4*)(g_ql + base);
        uint4* dh = (uint4*)(dynsm + SQH);
        uint4* dl = (uint4*)(dynsm + SQL);
        for (int i = tid; i < 1024; i += 512) {
            int row = i >> 3, ch = i & 7;
            int d = row * 8 + (ch ^ (row & 7));
            dh[d] = gh[i];
            dl[d] = gl[i];
        }
    }

    float o[8][4];
#pragma unroll
    for (int i = 0; i < 8; i++)
#pragma unroll
        for (int j = 0; j < 4; j++) o[i][j] = 0.0f;
    float m0 = -CUDART_INF_F, m1 = -CUDART_INF_F, l0 = 0.0f, l1 = 0.0f;

    for (int kt = 0; kt < 16; kt++) {
        __syncthreads();  // previous tile's ldmatrix reads done
        // ---- load K/V hi/lo tiles -------------------------------------
        {
            const size_t base = ((size_t)b * LK_ + kt * 128) * 64 * 2;
            const uint4* kh = (const uint4*)(g_kh + base);
            const uint4* kl = (const uint4*)(g_kl + base);
            const uint4* vh = (const uint4*)(g_vh + base);
            const uint4* vl = (const uint4*)(g_vl + base);
            uint4* dkh = (uint4*)(dynsm + SKH);
            uint4* dkl = (uint4*)(dynsm + SKL);
            uint4* dvh = (uint4*)(dynsm + SVH);
            uint4* dvl = (uint4*)(dynsm + SVL);
            for (int i = tid; i < 1024; i += 512) {
                int row = i >> 3, ch = i & 7;
                int d = row * 8 + (ch ^ (row & 7));
                dkh[d] = kh[i];
                dkl[d] = kl[i];
                dvh[d] = vh[i];
                dvl[d] = vl[i];
            }
        }
        __syncthreads();

        // ---- S = Q K^T (3-pass, interleaved) ----------------------------
        float c[8][4];
#pragma unroll
        for (int nt = 0; nt < 8; nt++)
#pragma unroll
            for (int j = 0; j < 4; j++) c[nt][j] = 0.0f;

#pragma unroll
        for (int ks = 0; ks < 4; ks++) {   // e = ks*16 .. +15
            uint32_t aqh[4], aql[4];
            {
                int arow = stripe + (lane & 7) + ((lane >> 3) & 1) * 8;
                int achunk = ks * 2 + (lane >> 4);
                uint32_t aoff = (uint32_t)(arow * 128 +
                                ((achunk ^ (arow & 7)) << 4));
                ldsm4(aqh, sb + SQH + aoff);
                ldsm4(aql, sb + SQL + aoff);
            }
            const int brow = lane & 7;
            const int bchunk = ks * 2 + ((lane >> 3) & 1);
            const int bsel = lane >> 4;
            uint32_t bf[8][2];
            uint32_t boffs[4];
#pragma unroll
            for (int np = 0; np < 4; np++) {
                int row = kbase + (np * 2 + bsel) * 8 + brow;
                boffs[np] = (uint32_t)(row * 128 + ((bchunk ^ (row & 7)) << 4));
                uint32_t t[4];
                ldsm4(t, sb + SKH + boffs[np]);
                bf[np * 2][0] = t[0]; bf[np * 2][1] = t[1];
                bf[np * 2 + 1][0] = t[2]; bf[np * 2 + 1][1] = t[3];
            }
#pragma unroll
            for (int nt = 0; nt < 8; nt++) mma16816(c[nt], aqh, bf[nt]);
#pragma unroll
            for (int nt = 0; nt < 8; nt++) mma16816(c[nt], aql, bf[nt]);
#pragma unroll
            for (int np = 0; np < 4; np++) {
                uint32_t t[4];
                ldsm4(t, sb + SKL + boffs[np]);
                bf[np * 2][0] = t[0]; bf[np * 2][1] = t[1];
                bf[np * 2 + 1][0] = t[2]; bf[np * 2 + 1][1] = t[3];
            }
#pragma unroll
            for (int nt = 0; nt < 8; nt++) mma16816(c[nt], aqh, bf[nt]);
        }

        // ---- online softmax (pair-combined via smem) --------------------
        float mx0 = -CUDART_INF_F, mx1 = -CUDART_INF_F;
#pragma unroll
        for (int nt = 0; nt < 8; nt++) {
            mx0 = fmaxf(mx0, fmaxf(c[nt][0], c[nt][1]));
            mx1 = fmaxf(mx1, fmaxf(c[nt][2], c[nt][3]));
        }
        mx0 = fmaxf(mx0, __shfl_xor_sync(0xffffffffu, mx0, 1));
        mx0 = fmaxf(mx0, __shfl_xor_sync(0xffffffffu, mx0, 2));
        mx1 = fmaxf(mx1, __shfl_xor_sync(0xffffffffu, mx1, 1));
        mx1 = fmaxf(mx1, __shfl_xor_sync(0xffffffffu, mx1, 2));
        if (tig == 0) {
            sRedM[half * 128 + r0] = mx0;
            sRedM[half * 128 + r1] = mx1;
        }
        __syncthreads();
        float gmx0 = fmaxf(sRedM[r0], sRedM[128 + r0]);
        float gmx1 = fmaxf(sRedM[r1], sRedM[128 + r1]);

        float nm0 = fmaxf(m0, gmx0), nm1 = fmaxf(m1, gmx1);
        float corr0 = __expf(m0 - nm0), corr1 = __expf(m1 - nm1);
        m0 = nm0; m1 = nm1;

        float s0 = 0.0f, s1 = 0.0f;
#pragma unroll
        for (int nt = 0; nt < 8; nt++) {
            c[nt][0] = __expf(c[nt][0] - m0);
            c[nt][1] = __expf(c[nt][1] - m0);
            c[nt][2] = __expf(c[nt][2] - m1);
            c[nt][3] = __expf(c[nt][3] - m1);
            s0 += c[nt][0] + c[nt][1];
            s1 += c[nt][2] + c[nt][3];
        }
        s0 += __shfl_xor_sync(0xffffffffu, s0, 1);
        s0 += __shfl_xor_sync(0xffffffffu, s0, 2);
        s1 += __shfl_xor_sync(0xffffffffu, s1, 1);
        s1 += __shfl_xor_sync(0xffffffffu, s1, 2);
        if (tig == 0) {
            sRedS[half * 128 + r0] = s0;
            sRedS[half * 128 + r1] = s1;
        }
        __syncthreads();
        l0 = l0 * corr0 + sRedS[r0] + sRedS[128 + r0];
        l1 = l1 * corr1 + sRedS[r1] + sRedS[128 + r1];

#pragma unroll
        for (int nt = 0; nt < 8; nt++) {
            o[nt][0] *= corr0; o[nt][1] *= corr0;
            o[nt][2] *= corr1; o[nt][3] *= corr1;
        }

        // ---- O += P V (2-pass: P single fp16, V hi/lo) ------------------
#pragma unroll
        for (int ks = 0; ks < 4; ks++) {   // keys = kbase + ks*16 .. +15
            uint32_t ah[4];
            ah[0] = pk2h(c[2 * ks][0], c[2 * ks][1]);
            ah[1] = pk2h(c[2 * ks][2], c[2 * ks][3]);
            ah[2] = pk2h(c[2 * ks + 1][0], c[2 * ks + 1][1]);
            ah[3] = pk2h(c[2 * ks + 1][2], c[2 * ks + 1][3]);

            const int vrow = kbase + ks * 16 + (lane & 15);
            const int vsel = lane >> 4;
            uint32_t bv[8][2];
            uint32_t voffs[4];
#pragma unroll
            for (int np = 0; np < 4; np++) {
                int chunk = np * 2 + vsel;
                voffs[np] = (uint32_t)(vrow * 128 + ((chunk ^ (vrow & 7)) << 4));
                uint32_t t[4];
                ldsm4t(t, sb + SVH + voffs[np]);
                bv[np * 2][0] = t[0]; bv[np * 2][1] = t[1];
                bv[np * 2 + 1][0] = t[2]; bv[np * 2 + 1][1] = t[3];
            }
#pragma unroll
            for (int nt = 0; nt < 8; nt++) mma16816(o[nt], ah, bv[nt]);
#pragma unroll
            for (int np = 0; np < 4; np++) {
                uint32_t t[4];
                ldsm4t(t, sb + SVL + voffs[np]);
                bv[np * 2][0] = t[0]; bv[np * 2][1] = t[1];
                bv[np * 2 + 1][0] = t[2]; bv[np * 2 + 1][1] = t[3];
            }
#pragma unroll
            for (int nt = 0; nt < 8; nt++) mma16816(o[nt], ah, bv[nt]);
        }
    }

    // ---- epilogue: combine warp-pair partial O, normalize, write --------
    __syncthreads();  // all smem tile reads done; reuse Q region as sO
    float* sO = (float*)dynsm;  // [128][64]
    if (half == 1) {
#pragma unroll
        for (int nt = 0; nt < 8; nt++) {
            int e = nt * 8 + 2 * tig;
            *(float2*)(sO + r0 * 64 + e) = make_float2(o[nt][0], o[nt][1]);
            *(float2*)(sO + r1 * 64 + e) = make_float2(o[nt][2], o[nt][3]);
        }
    }
    __syncthreads();
    if (half == 0) {
        float inv0 = 1.0f / l0, inv1 = 1.0f / l1;
        float* op = out + ((size_t)b * LQ_ + qt * 128) * E_;
#pragma unroll
        for (int nt = 0; nt < 8; nt++) {
            int e = nt * 8 + 2 * tig;
            float2 p0 = *(float2*)(sO + r0 * 64 + e);
            float2 p1 = *(float2*)(sO + r1 * 64 + e);
            *(float2*)(op + (size_t)r0 * E_ + e) =
                make_float2((o[nt][0] + p0.x) * inv0, (o[nt][1] + p0.y) * inv0);
            *(float2*)(op + (size_t)r1 * E_ + e) =
                make_float2((o[nt][2] + p1.x) * inv1, (o[nt][3] + p1.y) * inv1);
        }
    }
}

// ---------------------------------------------------------------------------
extern "C" void kernel_launch(void* const* d_in, const int* in_sizes, int n_in,
                              void* d_out, int out_size)
{
    const float* query = (const float*)d_in[0];
    const float* key   = (const float*)d_in[1];
    const float* Wq    = (const float*)d_in[2];
    const float* Wk    = (const float*)d_in[3];
    const float* Wv    = (const float*)d_in[4];

    cudaFuncSetAttribute(proj_kernel, cudaFuncAttributeMaxDynamicSharedMemorySize,
                         PROJ_SMEM_BYTES);
    cudaFuncSetAttribute(flash_kernel, cudaFuncAttributeMaxDynamicSharedMemorySize,
                         FLASH_SMEM_BYTES);

    dim3 gp(128, 3);
    proj_kernel<<<gp, 256, PROJ_SMEM_BYTES>>>(query, key, Wq, Wk, Wv);

    dim3 gf(LQ_ / 128, B_);
    flash_kernel<<<gf, 512, FLASH_SMEM_BYTES>>>((float*)d_out);
}

// round 14
// speedup vs baseline: 3.6791x; 1.1156x over previous
#include <cuda_runtime.h>
#include <cuda_fp16.h>
#include <math_constants.h>
#include <cstdint>

#define B_  8
#define LQ_ 2048
#define LK_ 2048
#define D_  128
#define E_  64

// Projected q/k as fp16 hi/lo, v as single fp16. Row-major [B*L][64].
#define PROJ_ELEMS (B_ * LQ_ * E_)
__device__ __align__(16) unsigned char g_qh[PROJ_ELEMS * 2];
__device__ __align__(16) unsigned char g_ql[PROJ_ELEMS * 2];
__device__ __align__(16) unsigned char g_kh[PROJ_ELEMS * 2];
__device__ __align__(16) unsigned char g_kl[PROJ_ELEMS * 2];
__device__ __align__(16) unsigned char g_vh[PROJ_ELEMS * 2];

// ============================ helpers ======================================
__device__ __forceinline__ uint32_t smem_u32(const void* p) {
    uint32_t a;
    asm("{ .reg .u64 t; cvta.to.shared.u64 t, %1; cvt.u32.u64 %0, t; }"
        : "=r"(a) : "l"(p));
    return a;
}
__device__ __forceinline__ unsigned pk2h(float a, float b) {
    __half2 h = __floats2half2_rn(a, b);
    return *reinterpret_cast<unsigned*>(&h);
}
__device__ __forceinline__ float f16_hi(float v) {
    return __half2float(__float2half_rn(v));
}

// D += A * B, m16n8k16, fp16 x fp16 -> f32
__device__ __forceinline__ void mma16816(float* d, const uint32_t* a,
                                         const uint32_t* b)
{
    asm volatile(
        "mma.sync.aligned.m16n8k16.row.col.f32.f16.f16.f32 "
        "{%0,%1,%2,%3}, {%4,%5,%6,%7}, {%8,%9}, {%0,%1,%2,%3};"
        : "+f"(d[0]), "+f"(d[1]), "+f"(d[2]), "+f"(d[3])
        : "r"(a[0]), "r"(a[1]), "r"(a[2]), "r"(a[3]), "r"(b[0]), "r"(b[1]));
}
__device__ __forceinline__ void ldsm4(uint32_t* r, uint32_t addr) {
    asm volatile("ldmatrix.sync.aligned.m8n8.x4.shared.b16 {%0,%1,%2,%3}, [%4];"
        : "=r"(r[0]), "=r"(r[1]), "=r"(r[2]), "=r"(r[3]) : "r"(addr));
}
__device__ __forceinline__ void ldsm4t(uint32_t* r, uint32_t addr) {
    asm volatile("ldmatrix.sync.aligned.m8n8.x4.trans.shared.b16 {%0,%1,%2,%3}, [%4];"
        : "=r"(r[0]), "=r"(r[1]), "=r"(r[2]), "=r"(r[3]) : "r"(addr));
}

// ===========================================================================
// Projection via 3-pass fp16 HMMA: out[row, 0:64] = X[row, 0:128] @ W[128,64].
// grid (128, 3): x = 128-row tile, y selects (q | k | v). 256 threads, 8 warps.
// q/k emit hi+lo; v emits hi only (PV uses single-fp16 V).
// Smem: Xh/Xl [128 rows][128 cols fp16] (256B rows), Wth/Wtl [64 n][128 k].
// XOR swizzle at 16B granularity: off = row*256 + ((ch^(row&7))<<4).
// ===========================================================================
#define PXH 0
#define PXL 32768
#define PWH 65536
#define PWL 81920
#define PROJ_SMEM_BYTES 98304

__global__ __launch_bounds__(256, 1) void proj_kernel(
    const float* __restrict__ query,
    const float* __restrict__ key,
    const float* __restrict__ Wq,
    const float* __restrict__ Wk,
    const float* __restrict__ Wv)
{
    extern __shared__ __align__(1024) unsigned char dynsm[];
    const uint32_t sb = smem_u32(dynsm);

    const float* X;
    const float* W;
    unsigned char* outh;
    unsigned char* outl;
    const int mat = blockIdx.y;
    if (mat == 0)      { X = query; W = Wq; outh = g_qh; outl = g_ql; }
    else if (mat == 1) { X = key;   W = Wk; outh = g_kh; outl = g_kl; }
    else               { X = key;   W = Wv; outh = g_vh; outl = 0; }

    const int tid = threadIdx.x;
    const int wid = tid >> 5;
    const int lane = tid & 31;
    const int gid = lane >> 2;
    const int tig = lane & 3;
    const int stripe = wid * 16;
    const int row0 = blockIdx.x * 128;

    // ---- split X tile into fp16 hi/lo, swizzled ------------------------
    for (int u = tid; u < 2048; u += 256) {       // (row, ch): 128 x 16
        int row = u >> 4, ch = u & 15;
        const float4* src = (const float4*)(X + (size_t)(row0 + row) * D_ + ch * 8);
        float4 a = src[0], bq = src[1];
        float h0 = f16_hi(a.x), h1 = f16_hi(a.y);
        float h2 = f16_hi(a.z), h3 = f16_hi(a.w);
        float h4 = f16_hi(bq.x), h5 = f16_hi(bq.y);
        float h6 = f16_hi(bq.z), h7 = f16_hi(bq.w);
        uint4 wh = make_uint4(pk2h(h0, h1), pk2h(h2, h3), pk2h(h4, h5), pk2h(h6, h7));
        uint4 wl = make_uint4(pk2h(a.x - h0, a.y - h1), pk2h(a.z - h2, a.w - h3),
                              pk2h(bq.x - h4, bq.y - h5), pk2h(bq.z - h6, bq.w - h7));
        uint32_t off = (uint32_t)(row * 256 + ((ch ^ (row & 7)) << 4));
        *(uint4*)(dynsm + PXH + off) = wh;
        *(uint4*)(dynsm + PXL + off) = wl;
    }
    // ---- split W^T into fp16 hi/lo, swizzled ---------------------------
    for (int u = tid; u < 1024; u += 256) {       // (n, ch): 64 x 16
        int n = u & 63, ch = u >> 6;
        float v[8];
#pragma unroll
        for (int t = 0; t < 8; t++) v[t] = W[(ch * 8 + t) * 64 + n];
        float h[8];
#pragma unroll
        for (int t = 0; t < 8; t++) h[t] = f16_hi(v[t]);
        uint4 wh = make_uint4(pk2h(h[0], h[1]), pk2h(h[2], h[3]),
                              pk2h(h[4], h[5]), pk2h(h[6], h[7]));
        uint4 wl = make_uint4(pk2h(v[0] - h[0], v[1] - h[1]),
                              pk2h(v[2] - h[2], v[3] - h[3]),
                              pk2h(v[4] - h[4], v[5] - h[5]),
                              pk2h(v[6] - h[6], v[7] - h[7]));
        uint32_t off = (uint32_t)(n * 256 + ((ch ^ (n & 7)) << 4));
        *(uint4*)(dynsm + PWH + off) = wh;
        *(uint4*)(dynsm + PWL + off) = wl;
    }
    __syncthreads();

    // ---- 3-pass HMMA: c = Xh*Wh + Xl*Wh + Xh*Wl ------------------------
    float c[8][4];
#pragma unroll
    for (int nt = 0; nt < 8; nt++)
#pragma unroll
        for (int j = 0; j < 4; j++) c[nt][j] = 0.0f;

#pragma unroll
    for (int ks = 0; ks < 8; ks++) {   // k = ks*16 .. +15
        uint32_t axh[4], axl[4];
        {
            int arow = stripe + (lane & 7) + ((lane >> 3) & 1) * 8;
            int achunk = ks * 2 + (lane >> 4);
            uint32_t aoff = (uint32_t)(arow * 256 + ((achunk ^ (arow & 7)) << 4));
            ldsm4(axh, sb + PXH + aoff);
            ldsm4(axl, sb + PXL + aoff);
        }
        const int brow7 = lane & 7;
        const int bchunk = ks * 2 + ((lane >> 3) & 1);
        const int bsel = lane >> 4;
        uint32_t bf[8][2];
        uint32_t boffs[4];
#pragma unroll
        for (int np = 0; np < 4; np++) {
            int n = (np * 2 + bsel) * 8 + brow7;
            boffs[np] = (uint32_t)(n * 256 + ((bchunk ^ (n & 7)) << 4));
            uint32_t t[4];
            ldsm4(t, sb + PWH + boffs[np]);
            bf[np * 2][0] = t[0]; bf[np * 2][1] = t[1];
            bf[np * 2 + 1][0] = t[2]; bf[np * 2 + 1][1] = t[3];
        }
#pragma unroll
        for (int nt = 0; nt < 8; nt++) mma16816(c[nt], axh, bf[nt]);
#pragma unroll
        for (int nt = 0; nt < 8; nt++) mma16816(c[nt], axl, bf[nt]);
#pragma unroll
        for (int np = 0; np < 4; np++) {
            uint32_t t[4];
            ldsm4(t, sb + PWL + boffs[np]);
            bf[np * 2][0] = t[0]; bf[np * 2][1] = t[1];
            bf[np * 2 + 1][0] = t[2]; bf[np * 2 + 1][1] = t[3];
        }
#pragma unroll
        for (int nt = 0; nt < 8; nt++) mma16816(c[nt], axh, bf[nt]);
    }

    // ---- epilogue: split fp32 result into fp16 hi/lo, row-major --------
    {
        int r0 = row0 + stripe + gid;
        int r1 = r0 + 8;
#pragma unroll
        for (int nt = 0; nt < 8; nt++) {
            int col = nt * 8 + 2 * tig;
            float h0 = f16_hi(c[nt][0]), h1 = f16_hi(c[nt][1]);
            float h2 = f16_hi(c[nt][2]), h3 = f16_hi(c[nt][3]);
            size_t o0 = ((size_t)r0 * 64 + col) * 2;
            size_t o1 = ((size_t)r1 * 64 + col) * 2;
            *(unsigned*)(outh + o0) = pk2h(h0, h1);
            *(unsigned*)(outh + o1) = pk2h(h2, h3);
            if (outl) {
                *(unsigned*)(outl + o0) = pk2h(c[nt][0] - h0, c[nt][1] - h1);
                *(unsigned*)(outl + o1) = pk2h(c[nt][2] - h2, c[nt][3] - h3);
            }
        }
    }
}

// ===========================================================================
// Flash attention via mma.sync m16n8k16 fp16.
// QK: 3-pass hi/lo compensation (Qh*Kh + Ql*Kh + Qh*Kl).
// PV: 1-pass — P single fp16, V single fp16 (V quant err ~2.4e-4 rel).
// grid (16, 8), 512 threads = 16 warps. Warp (rw = wid&7, half = wid>>3):
// 16 q-rows (rw*16..+15) x 64 keys (half*64..+63).
// Smem tiles [128][64] fp16, rows 128B, XOR-swizzled at 16B granularity.
// ===========================================================================
#define SQH 0
#define SQL 16384
#define SKH 32768
#define SKL 49152
#define SVH 65536
#define SRED 81920                       // sRedM[2][128], sRedS[2][128]
#define FLASH_SMEM_BYTES (81920 + 2048)

__global__ __launch_bounds__(512, 1) void flash_kernel(float* __restrict__ out)
{
    extern __shared__ __align__(1024) unsigned char dynsm[];
    const uint32_t sb = smem_u32(dynsm);

    const int tid = threadIdx.x;
    const int wid = tid >> 5;
    const int lane = tid & 31;
    const int gid = lane >> 2;    // row group within 8
    const int tig = lane & 3;     // col pair
    const int rw = wid & 7;
    const int half = wid >> 3;
    const int stripe = rw * 16;   // this warp's q-rows
    const int kbase = half * 64;  // this warp's keys
    const int b = blockIdx.y;
    const int qt = blockIdx.x;
    const int r0 = stripe + gid;
    const int r1 = r0 + 8;

    float* sRedM = (float*)(dynsm + SRED);   // [2][128]
    float* sRedS = sRedM + 256;              // [2][128]

    // ---- load Q hi/lo tiles into swizzled smem (resident) ---------------
    {
        const size_t base = ((size_t)b * LQ_ + qt * 128) * 64 * 2;  // bytes
        const uint4* gh = (const uint4*)(g_qh + base);
        const uint4* gl = (const uint4*)(g_ql + base);
        uint4* dh = (uint4*)(dynsm + SQH);
        uint4* dl = (uint4*)(dynsm + SQL);
        for (int i = tid; i < 1024; i += 512) {
            int row = i >> 3, ch = i & 7;
            int d = row * 8 + (ch ^ (row & 7));
            dh[d] = gh[i];
            dl[d] = gl[i];
        }
    }

    float o[8][4];
#pragma unroll
    for (int i = 0; i < 8; i++)
#pragma unroll
        for (int j = 0; j < 4; j++) o[i][j] = 0.0f;
    float m0 = -CUDART_INF_F, m1 = -CUDART_INF_F, l0 = 0.0f, l1 = 0.0f;

    for (int kt = 0; kt < 16; kt++) {
        __syncthreads();  // previous tile's ldmatrix reads done
        // ---- load K hi/lo + V hi tiles ---------------------------------
        {
            const size_t base = ((size_t)b * LK_ + kt * 128) * 64 * 2;
            const uint4* kh = (const uint4*)(g_kh + base);
            const uint4* kl = (const uint4*)(g_kl + base);
            const uint4* vh = (const uint4*)(g_vh + base);
            uint4* dkh = (uint4*)(dynsm + SKH);
            uint4* dkl = (uint4*)(dynsm + SKL);
            uint4* dvh = (uint4*)(dynsm + SVH);
            for (int i = tid; i < 1024; i += 512) {
                int row = i >> 3, ch = i & 7;
                int d = row * 8 + (ch ^ (row & 7));
                dkh[d] = kh[i];
                dkl[d] = kl[i];
                dvh[d] = vh[i];
            }
        }
        __syncthreads();

        // ---- S = Q K^T (3-pass, interleaved) ----------------------------
        float c[8][4];
#pragma unroll
        for (int nt = 0; nt < 8; nt++)
#pragma unroll
            for (int j = 0; j < 4; j++) c[nt][j] = 0.0f;

#pragma unroll
        for (int ks = 0; ks < 4; ks++) {   // e = ks*16 .. +15
            uint32_t aqh[4], aql[4];
            {
                int arow = stripe + (lane & 7) + ((lane >> 3) & 1) * 8;
                int achunk = ks * 2 + (lane >> 4);
                uint32_t aoff = (uint32_t)(arow * 128 +
                                ((achunk ^ (arow & 7)) << 4));
                ldsm4(aqh, sb + SQH + aoff);
                ldsm4(aql, sb + SQL + aoff);
            }
            const int brow = lane & 7;
            const int bchunk = ks * 2 + ((lane >> 3) & 1);
            const int bsel = lane >> 4;
            uint32_t bf[8][2];
            uint32_t boffs[4];
#pragma unroll
            for (int np = 0; np < 4; np++) {
                int row = kbase + (np * 2 + bsel) * 8 + brow;
                boffs[np] = (uint32_t)(row * 128 + ((bchunk ^ (row & 7)) << 4));
                uint32_t t[4];
                ldsm4(t, sb + SKH + boffs[np]);
                bf[np * 2][0] = t[0]; bf[np * 2][1] = t[1];
                bf[np * 2 + 1][0] = t[2]; bf[np * 2 + 1][1] = t[3];
            }
#pragma unroll
            for (int nt = 0; nt < 8; nt++) mma16816(c[nt], aqh, bf[nt]);
#pragma unroll
            for (int nt = 0; nt < 8; nt++) mma16816(c[nt], aql, bf[nt]);
#pragma unroll
            for (int np = 0; np < 4; np++) {
                uint32_t t[4];
                ldsm4(t, sb + SKL + boffs[np]);
                bf[np * 2][0] = t[0]; bf[np * 2][1] = t[1];
                bf[np * 2 + 1][0] = t[2]; bf[np * 2 + 1][1] = t[3];
            }
#pragma unroll
            for (int nt = 0; nt < 8; nt++) mma16816(c[nt], aqh, bf[nt]);
        }

        // ---- online softmax (pair-combined via smem) --------------------
        float mx0 = -CUDART_INF_F, mx1 = -CUDART_INF_F;
#pragma unroll
        for (int nt = 0; nt < 8; nt++) {
            mx0 = fmaxf(mx0, fmaxf(c[nt][0], c[nt][1]));
            mx1 = fmaxf(mx1, fmaxf(c[nt][2], c[nt][3]));
        }
        mx0 = fmaxf(mx0, __shfl_xor_sync(0xffffffffu, mx0, 1));
        mx0 = fmaxf(mx0, __shfl_xor_sync(0xffffffffu, mx0, 2));
        mx1 = fmaxf(mx1, __shfl_xor_sync(0xffffffffu, mx1, 1));
        mx1 = fmaxf(mx1, __shfl_xor_sync(0xffffffffu, mx1, 2));
        if (tig == 0) {
            sRedM[half * 128 + r0] = mx0;
            sRedM[half * 128 + r1] = mx1;
        }
        __syncthreads();
        float gmx0 = fmaxf(sRedM[r0], sRedM[128 + r0]);
        float gmx1 = fmaxf(sRedM[r1], sRedM[128 + r1]);

        float nm0 = fmaxf(m0, gmx0), nm1 = fmaxf(m1, gmx1);
        float corr0 = __expf(m0 - nm0), corr1 = __expf(m1 - nm1);
        m0 = nm0; m1 = nm1;

        float s0 = 0.0f, s1 = 0.0f;
#pragma unroll
        for (int nt = 0; nt < 8; nt++) {
            c[nt][0] = __expf(c[nt][0] - m0);
            c[nt][1] = __expf(c[nt][1] - m0);
            c[nt][2] = __expf(c[nt][2] - m1);
            c[nt][3] = __expf(c[nt][3] - m1);
            s0 += c[nt][0] + c[nt][1];
            s1 += c[nt][2] + c[nt][3];
        }
        s0 += __shfl_xor_sync(0xffffffffu, s0, 1);
        s0 += __shfl_xor_sync(0xffffffffu, s0, 2);
        s1 += __shfl_xor_sync(0xffffffffu, s1, 1);
        s1 += __shfl_xor_sync(0xffffffffu, s1, 2);
        if (tig == 0) {
            sRedS[half * 128 + r0] = s0;
            sRedS[half * 128 + r1] = s1;
        }
        __syncthreads();
        l0 = l0 * corr0 + sRedS[r0] + sRedS[128 + r0];
        l1 = l1 * corr1 + sRedS[r1] + sRedS[128 + r1];

#pragma unroll
        for (int nt = 0; nt < 8; nt++) {
            o[nt][0] *= corr0; o[nt][1] *= corr0;
            o[nt][2] *= corr1; o[nt][3] *= corr1;
        }

        // ---- O += P V (1-pass: P single fp16, V single fp16) ------------
#pragma unroll
        for (int ks = 0; ks < 4; ks++) {   // keys = kbase + ks*16 .. +15
            uint32_t ah[4];
            ah[0] = pk2h(c[2 * ks][0], c[2 * ks][1]);
            ah[1] = pk2h(c[2 * ks][2], c[2 * ks][3]);
            ah[2] = pk2h(c[2 * ks + 1][0], c[2 * ks + 1][1]);
            ah[3] = pk2h(c[2 * ks + 1][2], c[2 * ks + 1][3]);

            const int vrow = kbase + ks * 16 + (lane & 15);
            const int vsel = lane >> 4;
            uint32_t bv[8][2];
#pragma unroll
            for (int np = 0; np < 4; np++) {
                int chunk = np * 2 + vsel;
                uint32_t voff = (uint32_t)(vrow * 128 +
                                ((chunk ^ (vrow & 7)) << 4));
                uint32_t t[4];
                ldsm4t(t, sb + SVH + voff);
                bv[np * 2][0] = t[0]; bv[np * 2][1] = t[1];
                bv[np * 2 + 1][0] = t[2]; bv[np * 2 + 1][1] = t[3];
            }
#pragma unroll
            for (int nt = 0; nt < 8; nt++) mma16816(o[nt], ah, bv[nt]);
        }
    }

    // ---- epilogue: combine warp-pair partial O, normalize, write --------
    __syncthreads();  // all smem tile reads done; reuse Q region as sO
    float* sO = (float*)dynsm;  // [128][64]
    if (half == 1) {
#pragma unroll
        for (int nt = 0; nt < 8; nt++) {
            int e = nt * 8 + 2 * tig;
            *(float2*)(sO + r0 * 64 + e) = make_float2(o[nt][0], o[nt][1]);
            *(float2*)(sO + r1 * 64 + e) = make_float2(o[nt][2], o[nt][3]);
        }
    }
    __syncthreads();
    if (half == 0) {
        float inv0 = 1.0f / l0, inv1 = 1.0f / l1;
        float* op = out + ((size_t)b * LQ_ + qt * 128) * E_;
#pragma unroll
        for (int nt = 0; nt < 8; nt++) {
            int e = nt * 8 + 2 * tig;
            float2 p0 = *(float2*)(sO + r0 * 64 + e);
            float2 p1 = *(float2*)(sO + r1 * 64 + e);
            *(float2*)(op + (size_t)r0 * E_ + e) =
                make_float2((o[nt][0] + p0.x) * inv0, (o[nt][1] + p0.y) * inv0);
            *(float2*)(op + (size_t)r1 * E_ + e) =
                make_float2((o[nt][2] + p1.x) * inv1, (o[nt][3] + p1.y) * inv1);
        }
    }
}

// ---------------------------------------------------------------------------
extern "C" void kernel_launch(void* const* d_in, const int* in_sizes, int n_in,
                              void* d_out, int out_size)
{
    const float* query = (const float*)d_in[0];
    const float* key   = (const float*)d_in[1];
    const float* Wq    = (const float*)d_in[2];
    const float* Wk    = (const float*)d_in[3];
    const float* Wv    = (const float*)d_in[4];

    cudaFuncSetAttribute(proj_kernel, cudaFuncAttributeMaxDynamicSharedMemorySize,
                         PROJ_SMEM_BYTES);
    cudaFuncSetAttribute(flash_kernel, cudaFuncAttributeMaxDynamicSharedMemorySize,
                         FLASH_SMEM_BYTES);

    dim3 gp(128, 3);
    proj_kernel<<<gp, 256, PROJ_SMEM_BYTES>>>(query, key, Wq, Wk, Wv);

    dim3 gf(LQ_ / 128, B_);
    flash_kernel<<<gf, 512, FLASH_SMEM_BYTES>>>((float*)d_out);
}

// round 16
// speedup vs baseline: 4.6527x; 1.2646x over previous
#include <cuda_runtime.h>
#include <cuda_fp16.h>
#include <math_constants.h>
#include <cstdint>

#define B_  8
#define LQ_ 2048
#define LK_ 2048
#define D_  128
#define E_  64

// Projected q/k as fp16 hi/lo, v as single fp16. Row-major [B*L][64].
#define PROJ_ELEMS (B_ * LQ_ * E_)
__device__ __align__(16) unsigned char g_qh[PROJ_ELEMS * 2];
__device__ __align__(16) unsigned char g_ql[PROJ_ELEMS * 2];
__device__ __align__(16) unsigned char g_kh[PROJ_ELEMS * 2];
__device__ __align__(16) unsigned char g_kl[PROJ_ELEMS * 2];
__device__ __align__(16) unsigned char g_vh[PROJ_ELEMS * 2];

// ============================ helpers ======================================
__device__ __forceinline__ uint32_t smem_u32(const void* p) {
    uint32_t a;
    asm("{ .reg .u64 t; cvta.to.shared.u64 t, %1; cvt.u32.u64 %0, t; }"
        : "=r"(a) : "l"(p));
    return a;
}
__device__ __forceinline__ unsigned pk2h(float a, float b) {
    __half2 h = __floats2half2_rn(a, b);
    return *reinterpret_cast<unsigned*>(&h);
}
__device__ __forceinline__ float f16_hi(float v) {
    return __half2float(__float2half_rn(v));
}

// D += A * B, m16n8k16, fp16 x fp16 -> f32
__device__ __forceinline__ void mma16816(float* d, const uint32_t* a,
                                         const uint32_t* b)
{
    asm volatile(
        "mma.sync.aligned.m16n8k16.row.col.f32.f16.f16.f32 "
        "{%0,%1,%2,%3}, {%4,%5,%6,%7}, {%8,%9}, {%0,%1,%2,%3};"
        : "+f"(d[0]), "+f"(d[1]), "+f"(d[2]), "+f"(d[3])
        : "r"(a[0]), "r"(a[1]), "r"(a[2]), "r"(a[3]), "r"(b[0]), "r"(b[1]));
}
__device__ __forceinline__ void ldsm4(uint32_t* r, uint32_t addr) {
    asm volatile("ldmatrix.sync.aligned.m8n8.x4.shared.b16 {%0,%1,%2,%3}, [%4];"
        : "=r"(r[0]), "=r"(r[1]), "=r"(r[2]), "=r"(r[3]) : "r"(addr));
}
__device__ __forceinline__ void ldsm4t(uint32_t* r, uint32_t addr) {
    asm volatile("ldmatrix.sync.aligned.m8n8.x4.trans.shared.b16 {%0,%1,%2,%3}, [%4];"
        : "=r"(r[0]), "=r"(r[1]), "=r"(r[2]), "=r"(r[3]) : "r"(addr));
}

// ===========================================================================
// Projection via 3-pass fp16 HMMA (unchanged from R14 passing kernel).
// ===========================================================================
#define PXH 0
#define PXL 32768
#define PWH 65536
#define PWL 81920
#define PROJ_SMEM_BYTES 98304

__global__ __launch_bounds__(256, 1) void proj_kernel(
    const float* __restrict__ query,
    const float* __restrict__ key,
    const float* __restrict__ Wq,
    const float* __restrict__ Wk,
    const float* __restrict__ Wv)
{
    extern __shared__ __align__(1024) unsigned char dynsm[];
    const uint32_t sb = smem_u32(dynsm);

    const float* X;
    const float* W;
    unsigned char* outh;
    unsigned char* outl;
    const int mat = blockIdx.y;
    if (mat == 0)      { X = query; W = Wq; outh = g_qh; outl = g_ql; }
    else if (mat == 1) { X = key;   W = Wk; outh = g_kh; outl = g_kl; }
    else               { X = key;   W = Wv; outh = g_vh; outl = 0; }

    const int tid = threadIdx.x;
    const int wid = tid >> 5;
    const int lane = tid & 31;
    const int gid = lane >> 2;
    const int tig = lane & 3;
    const int stripe = wid * 16;
    const int row0 = blockIdx.x * 128;

    for (int u = tid; u < 2048; u += 256) {       // (row, ch): 128 x 16
        int row = u >> 4, ch = u & 15;
        const float4* src = (const float4*)(X + (size_t)(row0 + row) * D_ + ch * 8);
        float4 a = src[0], bq = src[1];
        float h0 = f16_hi(a.x), h1 = f16_hi(a.y);
        float h2 = f16_hi(a.z), h3 = f16_hi(a.w);
        float h4 = f16_hi(bq.x), h5 = f16_hi(bq.y);
        float h6 = f16_hi(bq.z), h7 = f16_hi(bq.w);
        uint4 wh = make_uint4(pk2h(h0, h1), pk2h(h2, h3), pk2h(h4, h5), pk2h(h6, h7));
        uint4 wl = make_uint4(pk2h(a.x - h0, a.y - h1), pk2h(a.z - h2, a.w - h3),
                              pk2h(bq.x - h4, bq.y - h5), pk2h(bq.z - h6, bq.w - h7));
        uint32_t off = (uint32_t)(row * 256 + ((ch ^ (row & 7)) << 4));
        *(uint4*)(dynsm + PXH + off) = wh;
        *(uint4*)(dynsm + PXL + off) = wl;
    }
    for (int u = tid; u < 1024; u += 256) {       // (n, ch): 64 x 16
        int n = u & 63, ch = u >> 6;
        float v[8];
#pragma unroll
        for (int t = 0; t < 8; t++) v[t] = W[(ch * 8 + t) * 64 + n];
        float h[8];
#pragma unroll
        for (int t = 0; t < 8; t++) h[t] = f16_hi(v[t]);
        uint4 wh = make_uint4(pk2h(h[0], h[1]), pk2h(h[2], h[3]),
                              pk2h(h[4], h[5]), pk2h(h[6], h[7]));
        uint4 wl = make_uint4(pk2h(v[0] - h[0], v[1] - h[1]),
                              pk2h(v[2] - h[2], v[3] - h[3]),
                              pk2h(v[4] - h[4], v[5] - h[5]),
                              pk2h(v[6] - h[6], v[7] - h[7]));
        uint32_t off = (uint32_t)(n * 256 + ((ch ^ (n & 7)) << 4));
        *(uint4*)(dynsm + PWH + off) = wh;
        *(uint4*)(dynsm + PWL + off) = wl;
    }
    __syncthreads();

    float c[8][4];
#pragma unroll
    for (int nt = 0; nt < 8; nt++)
#pragma unroll
        for (int j = 0; j < 4; j++) c[nt][j] = 0.0f;

#pragma unroll
    for (int ks = 0; ks < 8; ks++) {   // k = ks*16 .. +15
        uint32_t axh[4], axl[4];
        {
            int arow = stripe + (lane & 7) + ((lane >> 3) & 1) * 8;
            int achunk = ks * 2 + (lane >> 4);
            uint32_t aoff = (uint32_t)(arow * 256 + ((achunk ^ (arow & 7)) << 4));
            ldsm4(axh, sb + PXH + aoff);
            ldsm4(axl, sb + PXL + aoff);
        }
        const int brow7 = lane & 7;
        const int bchunk = ks * 2 + ((lane >> 3) & 1);
        const int bsel = lane >> 4;
        uint32_t bf[8][2];
        uint32_t boffs[4];
#pragma unroll
        for (int np = 0; np < 4; np++) {
            int n = (np * 2 + bsel) * 8 + brow7;
            boffs[np] = (uint32_t)(n * 256 + ((bchunk ^ (n & 7)) << 4));
            uint32_t t[4];
            ldsm4(t, sb + PWH + boffs[np]);
            bf[np * 2][0] = t[0]; bf[np * 2][1] = t[1];
            bf[np * 2 + 1][0] = t[2]; bf[np * 2 + 1][1] = t[3];
        }
#pragma unroll
        for (int nt = 0; nt < 8; nt++) mma16816(c[nt], axh, bf[nt]);
#pragma unroll
        for (int nt = 0; nt < 8; nt++) mma16816(c[nt], axl, bf[nt]);
#pragma unroll
        for (int np = 0; np < 4; np++) {
            uint32_t t[4];
            ldsm4(t, sb + PWL + boffs[np]);
            bf[np * 2][0] = t[0]; bf[np * 2][1] = t[1];
            bf[np * 2 + 1][0] = t[2]; bf[np * 2 + 1][1] = t[3];
        }
#pragma unroll
        for (int nt = 0; nt < 8; nt++) mma16816(c[nt], axh, bf[nt]);
    }

    {
        int r0 = row0 + stripe + gid;
        int r1 = r0 + 8;
#pragma unroll
        for (int nt = 0; nt < 8; nt++) {
            int col = nt * 8 + 2 * tig;
            float h0 = f16_hi(c[nt][0]), h1 = f16_hi(c[nt][1]);
            float h2 = f16_hi(c[nt][2]), h3 = f16_hi(c[nt][3]);
            size_t o0 = ((size_t)r0 * 64 + col) * 2;
            size_t o1 = ((size_t)r1 * 64 + col) * 2;
            *(unsigned*)(outh + o0) = pk2h(h0, h1);
            *(unsigned*)(outh + o1) = pk2h(h2, h3);
            if (outl) {
                *(unsigned*)(outl + o0) = pk2h(c[nt][0] - h0, c[nt][1] - h1);
                *(unsigned*)(outl + o1) = pk2h(c[nt][2] - h2, c[nt][3] - h3);
            }
        }
    }
}

// ===========================================================================
// Flash attention, fp16 HMMA. QK 3-pass hi/lo; PV 1-pass.
//  - cp.async double-buffered K/V tiles (48 KB/stage), 1 barrier per tile.
//  - Key-halves run fully independent (m,l,O) streams; merged once in the
//    epilogue with the exact two-stream softmax combine.
// grid (16, 8), 512 threads = 16 warps. Warp (rw = wid&7, half = wid>>3):
// 16 q-rows x 64 keys. Smem tiles [128 rows][64 fp16], XOR-swizzled 16B.
// ===========================================================================
#define SQH 0
#define SQL 16384
#define STAGE0 32768
#define STAGE_STRIDE 49152       // KH +0, KL +16384, VH +32768
#define SREDM 131072             // float[128]: half-1 m
#define SREDL 131584             // float[128]: half-1 l
#define FLASH_SMEM_BYTES 132096
// epilogue scratch sO [128][64] f32 overlays SQH/SQL (32 KB)

__device__ __forceinline__ void prefetch_tile(uint32_t sb, uint32_t stage_base,
                                              size_t gbase, int tid)
{
    const uint4* kh = (const uint4*)(g_kh + gbase);
    const uint4* kl = (const uint4*)(g_kl + gbase);
    const uint4* vh = (const uint4*)(g_vh + gbase);
#pragma unroll
    for (int j = 0; j < 6; j++) {
        int i = tid + j * 512;           // 0..3071
        int region = i >> 10;            // 0=KH 1=KL 2=VH
        int idx = i & 1023;
        int row = idx >> 3, ch = idx & 7;
        int d = row * 8 + (ch ^ (row & 7));
        const uint4* g = (region == 0 ? kh : (region == 1 ? kl : vh)) + idx;
        uint32_t s = sb + stage_base + (uint32_t)region * 16384u + (uint32_t)d * 16u;
        asm volatile("cp.async.cg.shared.global [%0], [%1], 16;"
                     :: "r"(s), "l"(g));
    }
    asm volatile("cp.async.commit_group;" ::: "memory");
}

__global__ __launch_bounds__(512, 1) void flash_kernel(float* __restrict__ out)
{
    extern __shared__ __align__(1024) unsigned char dynsm[];
    const uint32_t sb = smem_u32(dynsm);

    const int tid = threadIdx.x;
    const int wid = tid >> 5;
    const int lane = tid & 31;
    const int gid = lane >> 2;    // row group within 8
    const int tig = lane & 3;     // col pair
    const int rw = wid & 7;
    const int half = wid >> 3;
    const int stripe = rw * 16;   // this warp's q-rows
    const int kbase = half * 64;  // this warp's keys
    const int b = blockIdx.y;
    const int qt = blockIdx.x;
    const int r0 = stripe + gid;
    const int r1 = r0 + 8;

    const size_t kvrow0 = (size_t)b * LK_ * 64 * 2;   // byte base of batch

    // prefetch tile 0 while loading Q
    prefetch_tile(sb, STAGE0, kvrow0, tid);

    // ---- load Q hi/lo tiles into swizzled smem (resident) ---------------
    {
        const size_t base = ((size_t)b * LQ_ + qt * 128) * 64 * 2;  // bytes
        const uint4* gh = (const uint4*)(g_qh + base);
        const uint4* gl = (const uint4*)(g_ql + base);
        uint4* dh = (uint4*)(dynsm + SQH);
        uint4* dl = (uint4*)(dynsm + SQL);
        for (int i = tid; i < 1024; i += 512) {
            int row = i >> 3, ch = i & 7;
            int d = row * 8 + (ch ^ (row & 7));
            dh[d] = gh[i];
            dl[d] = gl[i];
        }
    }

    float o[8][4];
#pragma unroll
    for (int i = 0; i < 8; i++)
#pragma unroll
        for (int j = 0; j < 4; j++) o[i][j] = 0.0f;
    float mA = -CUDART_INF_F, mB = -CUDART_INF_F, lA = 0.0f, lB = 0.0f;

    for (int kt = 0; kt < 16; kt++) {
        asm volatile("cp.async.wait_group 0;" ::: "memory");
        __syncthreads();   // tile kt visible; all warps done with other buffer

        if (kt + 1 < 16)
            prefetch_tile(sb, STAGE0 + ((kt + 1) & 1) * STAGE_STRIDE,
                          kvrow0 + (size_t)(kt + 1) * 128 * 64 * 2, tid);

        const uint32_t sKH = STAGE0 + (kt & 1) * STAGE_STRIDE;
        const uint32_t sKL = sKH + 16384;
        const uint32_t sVH = sKH + 32768;

        // ---- S = Q K^T (3-pass, interleaved) ----------------------------
        float c[8][4];
#pragma unroll
        for (int nt = 0; nt < 8; nt++)
#pragma unroll
            for (int j = 0; j < 4; j++) c[nt][j] = 0.0f;

#pragma unroll
        for (int ks = 0; ks < 4; ks++) {   // e = ks*16 .. +15
            uint32_t aqh[4], aql[4];
            {
                int arow = stripe + (lane & 7) + ((lane >> 3) & 1) * 8;
                int achunk = ks * 2 + (lane >> 4);
                uint32_t aoff = (uint32_t)(arow * 128 +
                                ((achunk ^ (arow & 7)) << 4));
                ldsm4(aqh, sb + SQH + aoff);
                ldsm4(aql, sb + SQL + aoff);
            }
            const int brow = lane & 7;
            const int bchunk = ks * 2 + ((lane >> 3) & 1);
            const int bsel = lane >> 4;
            uint32_t bf[8][2];
            uint32_t boffs[4];
#pragma unroll
            for (int np = 0; np < 4; np++) {
                int row = kbase + (np * 2 + bsel) * 8 + brow;
                boffs[np] = (uint32_t)(row * 128 + ((bchunk ^ (row & 7)) << 4));
                uint32_t t[4];
                ldsm4(t, sb + sKH + boffs[np]);
                bf[np * 2][0] = t[0]; bf[np * 2][1] = t[1];
                bf[np * 2 + 1][0] = t[2]; bf[np * 2 + 1][1] = t[3];
            }
#pragma unroll
            for (int nt = 0; nt < 8; nt++) mma16816(c[nt], aqh, bf[nt]);
#pragma unroll
            for (int nt = 0; nt < 8; nt++) mma16816(c[nt], aql, bf[nt]);
#pragma unroll
            for (int np = 0; np < 4; np++) {
                uint32_t t[4];
                ldsm4(t, sb + sKL + boffs[np]);
                bf[np * 2][0] = t[0]; bf[np * 2][1] = t[1];
                bf[np * 2 + 1][0] = t[2]; bf[np * 2 + 1][1] = t[3];
            }
#pragma unroll
            for (int nt = 0; nt < 8; nt++) mma16816(c[nt], aqh, bf[nt]);
        }

        // ---- online softmax, warp-local only (per-half stream) ----------
        float mx0 = -CUDART_INF_F, mx1 = -CUDART_INF_F;
#pragma unroll
        for (int nt = 0; nt < 8; nt++) {
            mx0 = fmaxf(mx0, fmaxf(c[nt][0], c[nt][1]));
            mx1 = fmaxf(mx1, fmaxf(c[nt][2], c[nt][3]));
        }
        mx0 = fmaxf(mx0, __shfl_xor_sync(0xffffffffu, mx0, 1));
        mx0 = fmaxf(mx0, __shfl_xor_sync(0xffffffffu, mx0, 2));
        mx1 = fmaxf(mx1, __shfl_xor_sync(0xffffffffu, mx1, 1));
        mx1 = fmaxf(mx1, __shfl_xor_sync(0xffffffffu, mx1, 2));

        float nmA = fmaxf(mA, mx0), nmB = fmaxf(mB, mx1);
        float corrA = __expf(mA - nmA), corrB = __expf(mB - nmB);
        mA = nmA; mB = nmB;

        float s0 = 0.0f, s1 = 0.0f;
#pragma unroll
        for (int nt = 0; nt < 8; nt++) {
            c[nt][0] = __expf(c[nt][0] - mA);
            c[nt][1] = __expf(c[nt][1] - mA);
            c[nt][2] = __expf(c[nt][2] - mB);
            c[nt][3] = __expf(c[nt][3] - mB);
            s0 += c[nt][0] + c[nt][1];
            s1 += c[nt][2] + c[nt][3];
        }
        s0 += __shfl_xor_sync(0xffffffffu, s0, 1);
        s0 += __shfl_xor_sync(0xffffffffu, s0, 2);
        s1 += __shfl_xor_sync(0xffffffffu, s1, 1);
        s1 += __shfl_xor_sync(0xffffffffu, s1, 2);
        lA = lA * corrA + s0;
        lB = lB * corrB + s1;

#pragma unroll
        for (int nt = 0; nt < 8; nt++) {
            o[nt][0] *= corrA; o[nt][1] *= corrA;
            o[nt][2] *= corrB; o[nt][3] *= corrB;
        }

        // ---- O += P V (1-pass) ------------------------------------------
#pragma unroll
        for (int ks = 0; ks < 4; ks++) {   // keys = kbase + ks*16 .. +15
            uint32_t ah[4];
            ah[0] = pk2h(c[2 * ks][0], c[2 * ks][1]);
            ah[1] = pk2h(c[2 * ks][2], c[2 * ks][3]);
            ah[2] = pk2h(c[2 * ks + 1][0], c[2 * ks + 1][1]);
            ah[3] = pk2h(c[2 * ks + 1][2], c[2 * ks + 1][3]);

            const int vrow = kbase + ks * 16 + (lane & 15);
            const int vsel = lane >> 4;
            uint32_t bv[8][2];
#pragma unroll
            for (int np = 0; np < 4; np++) {
                int chunk = np * 2 + vsel;
                uint32_t voff = (uint32_t)(vrow * 128 +
                                ((chunk ^ (vrow & 7)) << 4));
                uint32_t t[4];
                ldsm4t(t, sb + sVH + voff);
                bv[np * 2][0] = t[0]; bv[np * 2][1] = t[1];
                bv[np * 2 + 1][0] = t[2]; bv[np * 2 + 1][1] = t[3];
            }
#pragma unroll
            for (int nt = 0; nt < 8; nt++) mma16816(o[nt], ah, bv[nt]);
        }
    }

    // ---- epilogue: merge half streams, normalize, write -----------------
    __syncthreads();               // all Q/smem reads done; reuse as scratch
    float* sO = (float*)dynsm;     // [128][64] overlays SQH/SQL
    float* sM1 = (float*)(dynsm + SREDM);
    float* sL1 = (float*)(dynsm + SREDL);
    if (half == 1) {
#pragma unroll
        for (int nt = 0; nt < 8; nt++) {
            int e = nt * 8 + 2 * tig;
            *(float2*)(sO + r0 * 64 + e) = make_float2(o[nt][0], o[nt][1]);
            *(float2*)(sO + r1 * 64 + e) = make_float2(o[nt][2], o[nt][3]);
        }
        if (tig == 0) { sM1[r0] = mA; sL1[r0] = lA; sM1[r1] = mB; sL1[r1] = lB; }
    }
    __syncthreads();
    if (half == 0) {
        // row r0: streams (mA,lA,o[.][0..1]) and (sM1[r0], sL1[r0], sO[r0])
        float m1r0 = sM1[r0], l1r0 = sL1[r0];
        float m1r1 = sM1[r1], l1r1 = sL1[r1];
        float mm0 = fmaxf(mA, m1r0), mm1 = fmaxf(mB, m1r1);
        float a00 = __expf(mA - mm0), a01 = __expf(m1r0 - mm0);
        float a10 = __expf(mB - mm1), a11 = __expf(m1r1 - mm1);
        float inv0 = 1.0f / (lA * a00 + l1r0 * a01);
        float inv1 = 1.0f / (lB * a10 + l1r1 * a11);
        float* op = out + ((size_t)b * LQ_ + qt * 128) * E_;
#pragma unroll
        for (int nt = 0; nt < 8; nt++) {
            int e = nt * 8 + 2 * tig;
            float2 p0 = *(float2*)(sO + r0 * 64 + e);
            float2 p1 = *(float2*)(sO + r1 * 64 + e);
            *(float2*)(op + (size_t)r0 * E_ + e) =
                make_float2((o[nt][0] * a00 + p0.x * a01) * inv0,
                            (o[nt][1] * a00 + p0.y * a01) * inv0);
            *(float2*)(op + (size_t)r1 * E_ + e) =
                make_float2((o[nt][2] * a10 + p1.x * a11) * inv1,
                            (o[nt][3] * a10 + p1.y * a11) * inv1);
        }
    }
}

// ---------------------------------------------------------------------------
extern "C" void kernel_launch(void* const* d_in, const int* in_sizes, int n_in,
                              void* d_out, int out_size)
{
    const float* query = (const float*)d_in[0];
    const float* key   = (const float*)d_in[1];
    const float* Wq    = (const float*)d_in[2];
    const float* Wk    = (const float*)d_in[3];
    const float* Wv    = (const float*)d_in[4];

    cudaFuncSetAttribute(proj_kernel, cudaFuncAttributeMaxDynamicSharedMemorySize,
                         PROJ_SMEM_BYTES);
    cudaFuncSetAttribute(flash_kernel, cudaFuncAttributeMaxDynamicSharedMemorySize,
                         FLASH_SMEM_BYTES);

    dim3 gp(128, 3);
    proj_kernel<<<gp, 256, PROJ_SMEM_BYTES>>>(query, key, Wq, Wk, Wv);

    dim3 gf(LQ_ / 128, B_);
    flash_kernel<<<gf, 512, FLASH_SMEM_BYTES>>>((float*)d_out);
}